// round 11
// baseline (speedup 1.0000x reference)
#include <cuda_runtime.h>
#include <math_constants.h>

#define BB 1024
#define VV 5000
#define NN 10000
#define TT 50
#define HH 200
#define KK 20

static __device__ __constant__ float c_ETA  = 0.5f;
static __device__ __constant__ float c_RHO  = 0.5f;
#define EPSV 1e-5f
#define CCV  0.25f
#define ALPHAV 1.0f

// ---------------- device scratch ----------------
__device__ float g_e1[BB*HH];
__device__ float g_e2[BB*HH];
__device__ float g_lin3[BB*TT];
__device__ float g_part[16*BB*256];
__device__ float g_soft[BB*TT];
__device__ float g_snorm[BB];
__device__ int   g_enc[BB];
__device__ int   g_counts[TT];
__device__ float g_mean3[TT];
__device__ float g_rstd3[TT];
__device__ float g_zc[TT*VV];
__device__ float g_zhat[TT*VV];
__device__ float g_lse[TT];
__device__ float g_banknorm[NN];
__device__ float g_fuse[(size_t)BB*NN];
__device__ int   g_topk[BB*KK];
__device__ int   g_w[NN*64];
__device__ int   g_used[NN];
__device__ double g_acc[2];

// ---------------- setup ----------------
__global__ void k_setup() {
    int i = blockIdx.x * 256 + threadIdx.x;
    if (i < NN * 64) g_w[i] = 0;
    if (i < NN) g_used[i] = 0;
    if (i < TT) g_counts[i] = 0;
    if (i < 2)  g_acc[i] = 0.0;
}

// ---------------- code logits (coalesced) ----------------
__global__ void k_zc(const float* __restrict__ Wd, const float* __restrict__ E) {
    __shared__ float Es[TT * TT];
    __shared__ float wS[128 * TT];
    int v0 = blockIdx.x * 128;
    for (int i = threadIdx.x; i < TT * TT; i += 128) Es[i] = E[i];
    for (int e = threadIdx.x; e < 128 * TT; e += 128) {
        int gidx = v0 * TT + e;
        wS[e] = (gidx < VV * TT) ? Wd[gidx] : 0.f;
    }
    __syncthreads();
    int v = v0 + threadIdx.x;
    if (v >= VV) return;
    float w[TT];
#pragma unroll
    for (int t = 0; t < TT; t++) w[t] = wS[threadIdx.x * TT + t];
    for (int c = 0; c < TT; c++) {
        float a = 0.f;
#pragma unroll
        for (int t = 0; t < TT; t++) a += Es[c * TT + t] * w[t];
        g_zc[(size_t)c * VV + v] = a;
    }
}

// ---------------- bank norms (coalesced) ----------------
__global__ void k_banknorm(const float* __restrict__ bank) {
    __shared__ float bS[128 * TT];
    int n0 = blockIdx.x * 128;
    for (int e = threadIdx.x; e < 128 * TT; e += 256) {
        int gidx = n0 * TT + e;
        bS[e] = (gidx < NN * TT) ? bank[gidx] : 0.f;
    }
    __syncthreads();
    if (threadIdx.x < 128) {
        int n = n0 + threadIdx.x;
        if (n < NN) {
            float s = 0.f;
#pragma unroll
            for (int t = 0; t < TT; t++) { float v = bS[threadIdx.x * TT + t]; s += v * v; }
            g_banknorm[n] = s;
        }
    }
}

// ---------------- f32x2 helpers ----------------
__device__ __forceinline__ void fma2(unsigned long long &c, unsigned long long a, unsigned long long b) {
    asm("fma.rn.f32x2 %0, %1, %2, %0;" : "+l"(c) : "l"(a), "l"(b));
}
__device__ __forceinline__ unsigned long long pack2(float x, float y) {
    unsigned long long r; asm("mov.b64 %0, {%1,%2};" : "=l"(r) : "f"(x), "f"(y));
    return r;
}
__device__ __forceinline__ float2 unpack2(unsigned long long v) {
    float2 r; asm("mov.b64 {%0,%1}, %2;" : "=f"(r.x), "=f"(r.y) : "l"(v));
    return r;
}

// ---------------- f32x2 NT GEMM ----------------
__global__ void k_gemm_f32x2(const float* __restrict__ Aext, const float* __restrict__ Bm,
                             int M, int Nmat, int Kdim, int lda, int ldb, int aSel) {
    const float* A = Aext;
    if (aSel == 1) A = g_e1; else if (aSel == 2) A = g_e2;

    const int BM = 128, BN = 64, BK = 16;
    __shared__ float As[BK][BM + 4];
    __shared__ float Bs[BK][BN + 4];

    int bm = blockIdx.x * BM, bn = blockIdx.y * BN;
    int s = blockIdx.z, Sn = gridDim.z;
    int kchunk = (((Kdim + Sn - 1) / Sn) + BK - 1) & ~(BK - 1);
    int k0 = s * kchunk, k1 = min(Kdim, k0 + kchunk);

    int tid = threadIdx.x;
    int tx = tid & 15, ty = tid >> 4;
    int alm = tid >> 1, alq = (tid & 1) * 8;
    int bln = tid >> 2, blq = (tid & 3) * 4;

    unsigned long long acc[4][4];
#pragma unroll
    for (int i = 0; i < 4; i++)
#pragma unroll
        for (int j = 0; j < 4; j++) acc[i][j] = 0ULL;

    if (k0 < k1) {
        float4 ar0, ar1, br0;
        {
            int kt = k0;
            int gk = kt + alq;
            const float* ap = A + (size_t)(bm + alm) * lda + gk;
            if (gk + 7 < k1) { ar0 = *(const float4*)ap; ar1 = *(const float4*)(ap + 4); }
            else {
                float t[8];
#pragma unroll
                for (int i = 0; i < 8; i++) t[i] = (gk + i < k1) ? ap[i] : 0.f;
                ar0 = make_float4(t[0], t[1], t[2], t[3]);
                ar1 = make_float4(t[4], t[5], t[6], t[7]);
            }
            int gkb = kt + blq;
            int brow = bn + bln;
            if (brow < Nmat && gkb + 3 < k1) br0 = *(const float4*)(Bm + (size_t)brow * ldb + gkb);
            else {
                float t[4];
#pragma unroll
                for (int i = 0; i < 4; i++)
                    t[i] = (brow < Nmat && gkb + i < k1) ? Bm[(size_t)brow * ldb + gkb + i] : 0.f;
                br0 = make_float4(t[0], t[1], t[2], t[3]);
            }
        }

        for (int kt = k0; kt < k1; kt += BK) {
            As[alq + 0][alm] = ar0.x; As[alq + 1][alm] = ar0.y;
            As[alq + 2][alm] = ar0.z; As[alq + 3][alm] = ar0.w;
            As[alq + 4][alm] = ar1.x; As[alq + 5][alm] = ar1.y;
            As[alq + 6][alm] = ar1.z; As[alq + 7][alm] = ar1.w;
            Bs[blq + 0][bln] = br0.x; Bs[blq + 1][bln] = br0.y;
            Bs[blq + 2][bln] = br0.z; Bs[blq + 3][bln] = br0.w;
            __syncthreads();

            int ktn = kt + BK;
            if (ktn < k1) {
                int gk = ktn + alq;
                const float* ap = A + (size_t)(bm + alm) * lda + gk;
                if (gk + 7 < k1) { ar0 = *(const float4*)ap; ar1 = *(const float4*)(ap + 4); }
                else {
                    float t[8];
#pragma unroll
                    for (int i = 0; i < 8; i++) t[i] = (gk + i < k1) ? ap[i] : 0.f;
                    ar0 = make_float4(t[0], t[1], t[2], t[3]);
                    ar1 = make_float4(t[4], t[5], t[6], t[7]);
                }
                int gkb = ktn + blq;
                int brow = bn + bln;
                if (brow < Nmat && gkb + 3 < k1) br0 = *(const float4*)(Bm + (size_t)brow * ldb + gkb);
                else {
                    float t[4];
#pragma unroll
                    for (int i = 0; i < 4; i++)
                        t[i] = (brow < Nmat && gkb + i < k1) ? Bm[(size_t)brow * ldb + gkb + i] : 0.f;
                    br0 = make_float4(t[0], t[1], t[2], t[3]);
                }
            }

#pragma unroll
            for (int kk = 0; kk < BK; kk++) {
                unsigned long long aP[4];
#pragma unroll
                for (int ip = 0; ip < 4; ip++)
                    aP[ip] = *(const unsigned long long*)&As[kk][ty * 8 + ip * 2];
                float4 bv = *(const float4*)&Bs[kk][tx * 4];
                unsigned long long b0 = pack2(bv.x, bv.x);
                unsigned long long b1 = pack2(bv.y, bv.y);
                unsigned long long b2 = pack2(bv.z, bv.z);
                unsigned long long b3 = pack2(bv.w, bv.w);
#pragma unroll
                for (int ip = 0; ip < 4; ip++) {
                    fma2(acc[ip][0], aP[ip], b0);
                    fma2(acc[ip][1], aP[ip], b1);
                    fma2(acc[ip][2], aP[ip], b2);
                    fma2(acc[ip][3], aP[ip], b3);
                }
            }
            __syncthreads();
        }
    }

    float* o = g_part + (size_t)s * BB * 256;
    int n0 = bn + tx * 4;
#pragma unroll
    for (int ip = 0; ip < 4; ip++) {
        int m0 = bm + ty * 8 + ip * 2;
        float2 c0 = unpack2(acc[ip][0]);
        float2 c1 = unpack2(acc[ip][1]);
        float2 c2 = unpack2(acc[ip][2]);
        float2 c3 = unpack2(acc[ip][3]);
        *(float4*)&o[(size_t)m0 * 256 + n0]       = make_float4(c0.x, c1.x, c2.x, c3.x);
        *(float4*)&o[(size_t)(m0 + 1) * 256 + n0] = make_float4(c0.y, c1.y, c2.y, c3.y);
    }
}

// reduce split-K partials + bias + optional softplus
__global__ void k_reduce_bias_act(int S, int Nreal, const float* __restrict__ bias,
                                  int act, int dstSel, int M) {
    int i = blockIdx.x * blockDim.x + threadIdx.x;
    int total = M * Nreal;
    if (i >= total) return;
    int m = i / Nreal, n = i - m * Nreal;
    float v = 0.f;
    for (int s = 0; s < S; s++) v += g_part[(size_t)s * BB * 256 + (size_t)m * 256 + n];
    v += bias[n];
    if (act == 1) v = (v > 0.f) ? v + log1pf(expf(-v)) : log1pf(expf(v));
    if (dstSel == 0)      g_e1  [(size_t)m * HH + n] = v;
    else if (dstSel == 1) g_e2  [(size_t)m * HH + n] = v;
    else                  g_lin3[(size_t)m * TT + n] = v;
}

// ---------------- theta BN stats ----------------
__global__ void k_bn_stats_theta() {
    int t = blockIdx.x;
    __shared__ float ssum[256], ssq[256];
    float s = 0.f, q = 0.f;
    for (int m = threadIdx.x; m < BB; m += 256) {
        float v = g_lin3[m * TT + t];
        s += v; q += v * v;
    }
    ssum[threadIdx.x] = s; ssq[threadIdx.x] = q;
    __syncthreads();
    for (int o = 128; o > 0; o >>= 1) {
        if (threadIdx.x < o) { ssum[threadIdx.x] += ssum[threadIdx.x + o]; ssq[threadIdx.x] += ssq[threadIdx.x + o]; }
        __syncthreads();
    }
    if (threadIdx.x == 0) {
        float mean = ssum[0] / BB;
        float var  = ssq[0] / BB - mean * mean;
        g_mean3[t] = mean;
        g_rstd3[t] = rsqrtf(var + EPSV);
    }
}

// ---------------- BN + softmax + VQ: one warp per batch row ----------------
__global__ void k_vq(const float* __restrict__ gm, const float* __restrict__ bm,
                     const float* __restrict__ E) {
    __shared__ float Es[TT * TT];
    __shared__ float sS[8][TT];
    int tid = threadIdx.x, lane = tid & 31, wid = tid >> 5;
    for (int i = tid; i < TT * TT; i += 256) Es[i] = E[i];
    __syncthreads();
    int b = blockIdx.x * 8 + wid;

    int t0 = lane, t1 = lane + 32;
    bool v0 = (t0 < TT), v1 = (t1 < TT);
    float th0 = v0 ? (g_lin3[b * TT + t0] - g_mean3[t0]) * g_rstd3[t0] * gm[t0] + bm[t0] : -CUDART_INF_F;
    float th1 = v1 ? (g_lin3[b * TT + t1] - g_mean3[t1]) * g_rstd3[t1] * gm[t1] + bm[t1] : -CUDART_INF_F;

    float mx = fmaxf(th0, th1);
#pragma unroll
    for (int o = 16; o > 0; o >>= 1) mx = fmaxf(mx, __shfl_xor_sync(0xffffffffu, mx, o));

    float ex0 = v0 ? expf(th0 - mx) : 0.f;
    float ex1 = v1 ? expf(th1 - mx) : 0.f;
    float sum = ex0 + ex1;
#pragma unroll
    for (int o = 16; o > 0; o >>= 1) sum += __shfl_xor_sync(0xffffffffu, sum, o);

    float s0 = ex0 / sum, s1 = ex1 / sum;
    if (v0) { g_soft[b * TT + t0] = s0; sS[wid][t0] = s0; }
    if (v1) { g_soft[b * TT + t1] = s1; sS[wid][t1] = s1; }

    float sn = s0 * s0 + (v1 ? s1 * s1 : 0.f);
#pragma unroll
    for (int o = 16; o > 0; o >>= 1) sn += __shfl_xor_sync(0xffffffffu, sn, o);
    if (lane == 0) g_snorm[b] = sn;
    __syncwarp();

    // distances for codes j = lane, lane+32
    float d0 = CUDART_INF_F, d1 = CUDART_INF_F;
    if (v0) {
        float dot = 0.f, en = 0.f;
#pragma unroll
        for (int u = 0; u < TT; u++) { float e = Es[t0 * TT + u]; dot += e * sS[wid][u]; en += e * e; }
        d0 = en - 2.f * dot;
    }
    if (v1) {
        float dot = 0.f, en = 0.f;
#pragma unroll
        for (int u = 0; u < TT; u++) { float e = Es[t1 * TT + u]; dot += e * sS[wid][u]; en += e * e; }
        d1 = en - 2.f * dot;
    }
    float bd = d0; int bj = t0;
    if (d1 < bd) { bd = d1; bj = t1; }
#pragma unroll
    for (int o = 16; o > 0; o >>= 1) {
        float ov = __shfl_xor_sync(0xffffffffu, bd, o);
        int   oi = __shfl_xor_sync(0xffffffffu, bj, o);
        if (ov < bd || (ov == bd && oi < bj)) { bd = ov; bj = oi; }
    }
    int jmin = bj;
    if (lane == 0) { g_enc[b] = jmin; atomicAdd(&g_counts[jmin], 1); }

    float df0 = v0 ? (Es[jmin * TT + t0] - s0) : 0.f;
    float df1 = v1 ? (Es[jmin * TT + t1] - s1) : 0.f;
    float el = df0 * df0 + df1 * df1;
#pragma unroll
    for (int o = 16; o > 0; o >>= 1) el += __shfl_xor_sync(0xffffffffu, el, o);
    if (lane == 0) atomicAdd(&g_acc[1], (double)el);
}

// ---------------- decoder BN ----------------
__global__ void k_decbn(const float* __restrict__ gd, const float* __restrict__ bd) {
    __shared__ float cnt[TT];
    for (int i = threadIdx.x; i < TT; i += 256) cnt[i] = (float)g_counts[i];
    __syncthreads();
    int v = blockIdx.x * 256 + threadIdx.x;
    if (v >= VV) return;
    float m = 0.f, q = 0.f;
    for (int c = 0; c < TT; c++) {
        float z = g_zc[(size_t)c * VV + v];
        m += cnt[c] * z; q += cnt[c] * z * z;
    }
    m /= BB; q /= BB;
    float rstd = rsqrtf(q - m * m + EPSV);
    float gg = gd[v], bbv = bd[v];
    for (int c = 0; c < TT; c++) {
        g_zhat[(size_t)c * VV + v] = (g_zc[(size_t)c * VV + v] - m) * rstd * gg + bbv;
    }
}

__global__ void k_lse() {
    int c = blockIdx.x;
    __shared__ float sm[256];
    const float* z = g_zhat + (size_t)c * VV;
    float mx = -CUDART_INF_F;
    for (int v = threadIdx.x; v < VV; v += 256) mx = fmaxf(mx, z[v]);
    sm[threadIdx.x] = mx; __syncthreads();
    for (int o = 128; o > 0; o >>= 1) { if (threadIdx.x < o) sm[threadIdx.x] = fmaxf(sm[threadIdx.x], sm[threadIdx.x + o]); __syncthreads(); }
    mx = sm[0]; __syncthreads();
    float s = 0.f;
    for (int v = threadIdx.x; v < VV; v += 256) s += expf(z[v] - mx);
    sm[threadIdx.x] = s; __syncthreads();
    for (int o = 128; o > 0; o >>= 1) { if (threadIdx.x < o) sm[threadIdx.x] += sm[threadIdx.x + o]; __syncthreads(); }
    if (threadIdx.x == 0) g_lse[c] = mx + logf(sm[0]);
}

// ---------------- distance GEMM + fuse epilogue (f32x2, 128x64 tiles) ----------------
__global__ void k_fuse(const float* __restrict__ bank, const float* __restrict__ Mcos,
                       const float* __restrict__ Mcoo, const int* __restrict__ idx) {
    __shared__ float As[TT][128 + 4];  // [k][m], stride 132 (8B-aligned rows)
    __shared__ float Bs[TT][64 + 4];   // [k][n], stride 68 (16B-aligned rows)
    int bm = blockIdx.x * 128, bn = blockIdx.y * 64;
    int tid = threadIdx.x;

    for (int e = tid; e < 128 * TT; e += 256) {
        int r = e / TT, kk = e - r * TT;
        As[kk][r] = g_soft[(size_t)(bm + r) * TT + kk];
    }
    for (int e = tid; e < 64 * TT; e += 256) {
        int r = e / TT, kk = e - r * TT;
        int nn = bn + r;
        Bs[kk][r] = (nn < NN) ? bank[(size_t)nn * TT + kk] : 0.f;
    }
    __syncthreads();

    int tx = tid & 15, ty = tid >> 4;
    unsigned long long acc[4][4];
#pragma unroll
    for (int i = 0; i < 4; i++)
#pragma unroll
        for (int j = 0; j < 4; j++) acc[i][j] = 0ULL;

#pragma unroll
    for (int kk = 0; kk < TT; kk++) {
        unsigned long long aP[4];
#pragma unroll
        for (int ip = 0; ip < 4; ip++)
            aP[ip] = *(const unsigned long long*)&As[kk][ty * 8 + ip * 2];
        float4 bv = *(const float4*)&Bs[kk][tx * 4];
        unsigned long long b0 = pack2(bv.x, bv.x);
        unsigned long long b1 = pack2(bv.y, bv.y);
        unsigned long long b2 = pack2(bv.z, bv.z);
        unsigned long long b3 = pack2(bv.w, bv.w);
#pragma unroll
        for (int ip = 0; ip < 4; ip++) {
            fma2(acc[ip][0], aP[ip], b0);
            fma2(acc[ip][1], aP[ip], b1);
            fma2(acc[ip][2], aP[ip], b2);
            fma2(acc[ip][3], aP[ip], b3);
        }
    }

    int n0 = bn + tx * 4;
    bool nok = (n0 + 3 < NN);
    float bn0 = 0, bn1 = 0, bn2 = 0, bn3 = 0;
    if (nok) { float4 t4 = *(const float4*)&g_banknorm[n0]; bn0 = t4.x; bn1 = t4.y; bn2 = t4.z; bn3 = t4.w; }
#pragma unroll
    for (int ip = 0; ip < 4; ip++) {
        float2 c0 = unpack2(acc[ip][0]);
        float2 c1 = unpack2(acc[ip][1]);
        float2 c2 = unpack2(acc[ip][2]);
        float2 c3 = unpack2(acc[ip][3]);
#pragma unroll
        for (int h = 0; h < 2; h++) {
            int m = bm + ty * 8 + ip * 2 + h;
            float dd0 = h ? c0.y : c0.x;
            float dd1 = h ? c1.y : c1.x;
            float dd2 = h ? c2.y : c2.x;
            float dd3 = h ? c3.y : c3.x;
            int ib = idx[m];
            float sn = g_snorm[m];
            size_t cbase = (size_t)ib * NN;
            if (nok) {
                float4 mc = *(const float4*)&Mcos[cbase + n0];
                float4 mo = *(const float4*)&Mcoo[cbase + n0];
                float cost, tdd, bow;
                float4 fo;
                cost = sn + bn0 - 2.f * dd0; tdd = cost * cost;
                bow = c_RHO * mc.x + (1.f - c_RHO) * mo.x;
                fo.x = (n0     == ib) ? CUDART_INF_F : c_ETA * tdd + (1.f - c_ETA) * bow;
                cost = sn + bn1 - 2.f * dd1; tdd = cost * cost;
                bow = c_RHO * mc.y + (1.f - c_RHO) * mo.y;
                fo.y = (n0 + 1 == ib) ? CUDART_INF_F : c_ETA * tdd + (1.f - c_ETA) * bow;
                cost = sn + bn2 - 2.f * dd2; tdd = cost * cost;
                bow = c_RHO * mc.z + (1.f - c_RHO) * mo.z;
                fo.z = (n0 + 2 == ib) ? CUDART_INF_F : c_ETA * tdd + (1.f - c_ETA) * bow;
                cost = sn + bn3 - 2.f * dd3; tdd = cost * cost;
                bow = c_RHO * mc.w + (1.f - c_RHO) * mo.w;
                fo.w = (n0 + 3 == ib) ? CUDART_INF_F : c_ETA * tdd + (1.f - c_ETA) * bow;
                *(float4*)&g_fuse[(size_t)m * NN + n0] = fo;
            } else {
                float dds[4] = {dd0, dd1, dd2, dd3};
#pragma unroll
                for (int j = 0; j < 4; j++) {
                    int n = n0 + j;
                    if (n < NN) {
                        float cost = sn + g_banknorm[n] - 2.f * dds[j];
                        float tdd = cost * cost;
                        float bow = c_RHO * Mcos[cbase + n] + (1.f - c_RHO) * Mcoo[cbase + n];
                        float f = (n == ib) ? CUDART_INF_F : c_ETA * tdd + (1.f - c_ETA) * bow;
                        g_fuse[(size_t)m * NN + n] = f;
                    }
                }
            }
        }
    }
}

// ---------------- warp argmin ----------------
__device__ __forceinline__ void warpmin(float &v, int &i) {
#pragma unroll
    for (int o = 16; o > 0; o >>= 1) {
        float ov = __shfl_xor_sync(0xffffffffu, v, o);
        int   oi = __shfl_xor_sync(0xffffffffu, i, o);
        if (ov < v || (ov == v && oi < i)) { v = ov; i = oi; }
    }
}

// ---------------- top-K (register lists, static indexing) ----------------
__global__ void k_topk(const int* __restrict__ is_aug, int do_scatter) {
    int b = blockIdx.x;
    const float* row = g_fuse + (size_t)b * NN;
    int tid = threadIdx.x, lane = tid & 31, wid = tid >> 5;

    float val[KK]; int ind[KK];
#pragma unroll
    for (int i = 0; i < KK; i++) { val[i] = CUDART_INF_F; ind[i] = 0x7fffffff; }
    for (int n = tid; n < NN; n += 256) {
        float f = row[n];
        if (f < val[KK - 1] || (f == val[KK - 1] && n < ind[KK - 1])) {
            float cf = f; int cn = n;
#pragma unroll
            for (int i = 0; i < KK; i++) {
                bool sw = (cf < val[i]) || (cf == val[i] && cn < ind[i]);
                float tv = val[i]; int ti = ind[i];
                if (sw) { val[i] = cf; ind[i] = cn; cf = tv; cn = ti; }
            }
        }
    }

    __shared__ float swv[8 * KK];
    __shared__ int   swi[8 * KK];
    for (int sel = 0; sel < KK; sel++) {
        float bv = val[0]; int bi = ind[0];
        int hi = ind[0];
        warpmin(bv, bi);
        if (hi == bi) {
#pragma unroll
            for (int i = 0; i < KK - 1; i++) { val[i] = val[i + 1]; ind[i] = ind[i + 1]; }
            val[KK - 1] = CUDART_INF_F; ind[KK - 1] = 0x7fffffff;
        }
        if (lane == 0) { swv[wid * KK + sel] = bv; swi[wid * KK + sel] = bi; }
    }
    __syncthreads();

    if (wid == 0) {
        float v5[5]; int i5[5];
#pragma unroll
        for (int t = 0; t < 5; t++) { v5[t] = swv[lane * 5 + t]; i5[t] = swi[lane * 5 + t]; }
        int topn[KK];
#pragma unroll 1
        for (int sel = 0; sel < KK; sel++) {
            float bv = v5[0]; int bi = i5[0];
            int hi = i5[0];
            warpmin(bv, bi);
            if (hi == bi) {
#pragma unroll
                for (int i = 0; i < 4; i++) { v5[i] = v5[i + 1]; i5[i] = i5[i + 1]; }
                v5[4] = CUDART_INF_F; i5[4] = 0x7fffffff;
            }
            if (lane == 0) { g_topk[b * KK + sel] = bi; topn[sel] = bi; }
        }
        if (lane == 0 && do_scatter && is_aug[0] != 0) {
            int e = g_enc[b];
#pragma unroll
            for (int k = 0; k < KK; k++) {
                int n = topn[k];
                atomicAdd(&g_w[n * 64 + e], 1);
                g_used[n] = 1;
            }
        }
    }
}

// ---------------- per-unique-row rec contribution ----------------
__global__ void k_recrows(const float* __restrict__ training, const int* __restrict__ is_aug) {
    if (is_aug[0] == 0) return;
    int n = blockIdx.x;
    if (!g_used[n]) return;
    __shared__ float trS[VV];
    __shared__ int codes[64];
    __shared__ int wts[64];
    __shared__ int s_nc;
    __shared__ float red[256];
    __shared__ float s_S;
    __shared__ double warpc[8];
    int tid = threadIdx.x, lane = tid & 31, wid = tid >> 5;
    if (tid == 0) s_nc = 0;
    if (tid < 8) warpc[tid] = 0.0;
    __syncthreads();
    if (tid < 64) {
        int w = g_w[n * 64 + tid];
        if (w > 0) { int pp = atomicAdd(&s_nc, 1); codes[pp] = tid; wts[pp] = w; }
    }
    const float* tr = training + (size_t)n * VV;
    float sloc = 0.f;
    for (int v = tid * 4; v < VV; v += 256 * 4) {
        float4 x = *(const float4*)(tr + v);
        *(float4*)&trS[v] = x;
        sloc += x.x + x.y + x.z + x.w;
    }
    red[tid] = sloc; __syncthreads();
    for (int o = 128; o > 0; o >>= 1) { if (tid < o) red[tid] += red[tid + o]; __syncthreads(); }
    if (tid == 0) s_S = red[0];
    __syncthreads();

    int nc = s_nc;
    float S = s_S;
    for (int ci = wid; ci < nc; ci += 8) {
        int c = codes[ci];
        const float* z = g_zhat + (size_t)c * VV;
        float d = 0.f;
        for (int v = lane * 4; v < VV; v += 128) {
            float4 x = *(const float4*)&trS[v];
            float4 zz = *(const float4*)(z + v);
            d += x.x * zz.x + x.y * zz.y + x.z * zz.z + x.w * zz.w;
        }
#pragma unroll
        for (int o = 16; o > 0; o >>= 1) d += __shfl_xor_sync(0xffffffffu, d, o);
        if (lane == 0) warpc[wid] += (double)wts[ci] * ((double)g_lse[c] * (double)S - (double)d);
    }
    __syncthreads();
    if (tid == 0) {
        double contrib = 0.0;
#pragma unroll
        for (int w = 0; w < 8; w++) contrib += warpc[w];
        if (nc > 0) atomicAdd(&g_acc[0], contrib * (double)(ALPHAV / (float)KK));
    }
}

// ---------------- inputs part of rec loss ----------------
__global__ void k_recinput(const float* __restrict__ inputs) {
    int b = blockIdx.x;
    int e = g_enc[b];
    const float* z  = g_zhat + (size_t)e * VV;
    const float* xr = inputs + (size_t)b * VV;
    int tid = threadIdx.x;
    float dotI = 0.f, sumI = 0.f;
    for (int v = tid * 4; v < VV; v += 256 * 4) {
        float4 x = *(const float4*)(xr + v);
        float4 zz = *(const float4*)(z + v);
        dotI += x.x * zz.x + x.y * zz.y + x.z * zz.z + x.w * zz.w;
        sumI += x.x + x.y + x.z + x.w;
    }
    __shared__ float r1[256], r2[256];
    r1[tid] = dotI; r2[tid] = sumI;
    __syncthreads();
    for (int o = 128; o > 0; o >>= 1) {
        if (tid < o) { r1[tid] += r1[tid + o]; r2[tid] += r2[tid + o]; }
        __syncthreads();
    }
    if (tid == 0) {
        double contrib = (double)g_lse[e] * (double)r2[0] - (double)r1[0];
        atomicAdd(&g_acc[0], contrib);
    }
}

// ---------------- final ----------------
__global__ void k_final(float* out) {
    if (threadIdx.x == 0) {
        double rec = g_acc[0] / (double)BB;
        double ql  = (1.0 + (double)CCV) * (g_acc[1] / (double)(BB * TT));
        out[0] = (float)(rec + ql);
    }
}

// ---------------- launch ----------------
extern "C" void kernel_launch(void* const* d_in, const int* in_sizes, int n_in,
                              void* d_out, int out_size) {
    const int*   idx      = (const int*)  d_in[0];
    const float* inputs   = (const float*)d_in[1];
    const int*   is_aug   = (const int*)  d_in[2];
    const float* training = (const float*)d_in[3];
    const float* Mcos     = (const float*)d_in[4];
    const float* Mcoo     = (const float*)d_in[5];
    const float* bank     = (const float*)d_in[6];
    const float* W11      = (const float*)d_in[7];
    const float* b11      = (const float*)d_in[8];
    const float* W12      = (const float*)d_in[9];
    const float* b12      = (const float*)d_in[10];
    const float* W21      = (const float*)d_in[11];
    const float* b21      = (const float*)d_in[12];
    const float* gm       = (const float*)d_in[13];
    const float* bm       = (const float*)d_in[14];
    const float* gd       = (const float*)d_in[15];
    const float* bd       = (const float*)d_in[16];
    const float* Wd       = (const float*)d_in[17];
    const float* E        = (const float*)d_in[18];
    float* out = (float*)d_out;

    k_setup<<<(NN * 64 + 255) / 256, 256>>>();
    k_zc<<<(VV + 127) / 128, 128>>>(Wd, E);
    k_banknorm<<<(NN + 127) / 128, 256>>>(bank);

    // launch 4: PROBE topk (no side effects; g_topk overwritten by real topk) -> ncu captures
    k_topk<<<BB, 256>>>(is_aug, 0);

    // encoder layer 1 (f32x2), split-K=16 -> 512 blocks
    k_gemm_f32x2<<<dim3(8, 4, 16), 256>>>(inputs, W11, BB, HH, VV, VV, VV, 0);
    k_reduce_bias_act<<<(BB * HH + 255) / 256, 256>>>(16, HH, b11, 1, 0, BB);

    // encoder layer 2
    k_gemm_f32x2<<<dim3(8, 4, 4), 256>>>(nullptr, W12, BB, HH, HH, HH, HH, 1);
    k_reduce_bias_act<<<(BB * HH + 255) / 256, 256>>>(4, HH, b12, 1, 1, BB);

    // theta linear
    k_gemm_f32x2<<<dim3(8, 1, 4), 256>>>(nullptr, W21, BB, TT, HH, HH, HH, 2);
    k_reduce_bias_act<<<(BB * TT + 255) / 256, 256>>>(4, TT, b21, 0, 2, BB);

    // BN stats + VQ (warp-per-row)
    k_bn_stats_theta<<<TT, 256>>>();
    k_vq<<<BB / 8, 256>>>(gm, bm, E);

    // decoder per-code pipeline
    k_decbn<<<(VV + 255) / 256, 256>>>(gd, bd);
    k_lse<<<TT, 256>>>();

    // augmentation: fuse (f32x2 tiles) + topk
    k_fuse<<<dim3(8, (NN + 63) / 64), 256>>>(bank, Mcos, Mcoo, idx);
    k_topk<<<BB, 256>>>(is_aug, 1);

    // rec loss
    k_recrows<<<NN, 256>>>(training, is_aug);
    k_recinput<<<BB, 256>>>(inputs);
    k_final<<<1, 1>>>(out);
}

// round 13
// speedup vs baseline: 2.3560x; 2.3560x over previous
#include <cuda_runtime.h>
#include <math_constants.h>

#define BB 1024
#define VV 5000
#define NN 10000
#define TT 50
#define HH 200
#define KK 20

static __device__ __constant__ float c_ETA  = 0.5f;
static __device__ __constant__ float c_RHO  = 0.5f;
#define EPSV 1e-5f
#define CCV  0.25f
#define ALPHAV 1.0f

// ---------------- device scratch ----------------
__device__ float g_e1[BB*HH];
__device__ float g_e2[BB*HH];
__device__ float g_lin3[BB*TT];
__device__ float g_part[16*BB*256];
__device__ float g_soft[BB*TT];
__device__ float g_snorm[BB];
__device__ int   g_enc[BB];
__device__ int   g_counts[TT];
__device__ float g_mean3[TT];
__device__ float g_rstd3[TT];
__device__ float g_zc[TT*VV];
__device__ float g_zhat[TT*VV];
__device__ float g_lse[TT];
__device__ float g_banknorm[NN];
__device__ float g_fuse[(size_t)BB*NN];
__device__ int   g_w[NN*64];
__device__ int   g_used[NN];
__device__ double g_acc[2];

// ---------------- setup ----------------
__global__ void k_setup() {
    int i = blockIdx.x * 256 + threadIdx.x;
    if (i < NN * 64) g_w[i] = 0;
    if (i < NN) g_used[i] = 0;
    if (i < TT) g_counts[i] = 0;
    if (i < 2)  g_acc[i] = 0.0;
}

// ---------------- code logits (coalesced) ----------------
__global__ void k_zc(const float* __restrict__ Wd, const float* __restrict__ E) {
    __shared__ float Es[TT * TT];
    __shared__ float wS[128 * TT];
    int v0 = blockIdx.x * 128;
    for (int i = threadIdx.x; i < TT * TT; i += 128) Es[i] = E[i];
    for (int e = threadIdx.x; e < 128 * TT; e += 128) {
        int gidx = v0 * TT + e;
        wS[e] = (gidx < VV * TT) ? Wd[gidx] : 0.f;
    }
    __syncthreads();
    int v = v0 + threadIdx.x;
    if (v >= VV) return;
    float w[TT];
#pragma unroll
    for (int t = 0; t < TT; t++) w[t] = wS[threadIdx.x * TT + t];
    for (int c = 0; c < TT; c++) {
        float a = 0.f;
#pragma unroll
        for (int t = 0; t < TT; t++) a += Es[c * TT + t] * w[t];
        g_zc[(size_t)c * VV + v] = a;
    }
}

// ---------------- bank norms (coalesced) ----------------
__global__ void k_banknorm(const float* __restrict__ bank) {
    __shared__ float bS[128 * TT];
    int n0 = blockIdx.x * 128;
    for (int e = threadIdx.x; e < 128 * TT; e += 256) {
        int gidx = n0 * TT + e;
        bS[e] = (gidx < NN * TT) ? bank[gidx] : 0.f;
    }
    __syncthreads();
    if (threadIdx.x < 128) {
        int n = n0 + threadIdx.x;
        if (n < NN) {
            float s = 0.f;
#pragma unroll
            for (int t = 0; t < TT; t++) { float v = bS[threadIdx.x * TT + t]; s += v * v; }
            g_banknorm[n] = s;
        }
    }
}

// ---------------- f32x2 helpers ----------------
__device__ __forceinline__ void fma2(unsigned long long &c, unsigned long long a, unsigned long long b) {
    asm("fma.rn.f32x2 %0, %1, %2, %0;" : "+l"(c) : "l"(a), "l"(b));
}
__device__ __forceinline__ unsigned long long pack2(float x, float y) {
    unsigned long long r; asm("mov.b64 %0, {%1,%2};" : "=l"(r) : "f"(x), "f"(y));
    return r;
}
__device__ __forceinline__ float2 unpack2(unsigned long long v) {
    float2 r; asm("mov.b64 {%0,%1}, %2;" : "=f"(r.x), "=f"(r.y) : "l"(v));
    return r;
}

// ---------------- f32x2 NT GEMM ----------------
__global__ void k_gemm_f32x2(const float* __restrict__ Aext, const float* __restrict__ Bm,
                             int M, int Nmat, int Kdim, int lda, int ldb, int aSel) {
    const float* A = Aext;
    if (aSel == 1) A = g_e1; else if (aSel == 2) A = g_e2;

    const int BM = 128, BN = 64, BK = 16;
    __shared__ float As[BK][BM + 4];
    __shared__ float Bs[BK][BN + 4];

    int bm = blockIdx.x * BM, bn = blockIdx.y * BN;
    int s = blockIdx.z, Sn = gridDim.z;
    int kchunk = (((Kdim + Sn - 1) / Sn) + BK - 1) & ~(BK - 1);
    int k0 = s * kchunk, k1 = min(Kdim, k0 + kchunk);

    int tid = threadIdx.x;
    int tx = tid & 15, ty = tid >> 4;
    int alm = tid >> 1, alq = (tid & 1) * 8;
    int bln = tid >> 2, blq = (tid & 3) * 4;

    unsigned long long acc[4][4];
#pragma unroll
    for (int i = 0; i < 4; i++)
#pragma unroll
        for (int j = 0; j < 4; j++) acc[i][j] = 0ULL;

    if (k0 < k1) {
        float4 ar0, ar1, br0;
        {
            int kt = k0;
            int gk = kt + alq;
            const float* ap = A + (size_t)(bm + alm) * lda + gk;
            if (gk + 7 < k1) { ar0 = *(const float4*)ap; ar1 = *(const float4*)(ap + 4); }
            else {
                float t[8];
#pragma unroll
                for (int i = 0; i < 8; i++) t[i] = (gk + i < k1) ? ap[i] : 0.f;
                ar0 = make_float4(t[0], t[1], t[2], t[3]);
                ar1 = make_float4(t[4], t[5], t[6], t[7]);
            }
            int gkb = kt + blq;
            int brow = bn + bln;
            if (brow < Nmat && gkb + 3 < k1) br0 = *(const float4*)(Bm + (size_t)brow * ldb + gkb);
            else {
                float t[4];
#pragma unroll
                for (int i = 0; i < 4; i++)
                    t[i] = (brow < Nmat && gkb + i < k1) ? Bm[(size_t)brow * ldb + gkb + i] : 0.f;
                br0 = make_float4(t[0], t[1], t[2], t[3]);
            }
        }

        for (int kt = k0; kt < k1; kt += BK) {
            As[alq + 0][alm] = ar0.x; As[alq + 1][alm] = ar0.y;
            As[alq + 2][alm] = ar0.z; As[alq + 3][alm] = ar0.w;
            As[alq + 4][alm] = ar1.x; As[alq + 5][alm] = ar1.y;
            As[alq + 6][alm] = ar1.z; As[alq + 7][alm] = ar1.w;
            Bs[blq + 0][bln] = br0.x; Bs[blq + 1][bln] = br0.y;
            Bs[blq + 2][bln] = br0.z; Bs[blq + 3][bln] = br0.w;
            __syncthreads();

            int ktn = kt + BK;
            if (ktn < k1) {
                int gk = ktn + alq;
                const float* ap = A + (size_t)(bm + alm) * lda + gk;
                if (gk + 7 < k1) { ar0 = *(const float4*)ap; ar1 = *(const float4*)(ap + 4); }
                else {
                    float t[8];
#pragma unroll
                    for (int i = 0; i < 8; i++) t[i] = (gk + i < k1) ? ap[i] : 0.f;
                    ar0 = make_float4(t[0], t[1], t[2], t[3]);
                    ar1 = make_float4(t[4], t[5], t[6], t[7]);
                }
                int gkb = ktn + blq;
                int brow = bn + bln;
                if (brow < Nmat && gkb + 3 < k1) br0 = *(const float4*)(Bm + (size_t)brow * ldb + gkb);
                else {
                    float t[4];
#pragma unroll
                    for (int i = 0; i < 4; i++)
                        t[i] = (brow < Nmat && gkb + i < k1) ? Bm[(size_t)brow * ldb + gkb + i] : 0.f;
                    br0 = make_float4(t[0], t[1], t[2], t[3]);
                }
            }

#pragma unroll
            for (int kk = 0; kk < BK; kk++) {
                unsigned long long aP[4];
#pragma unroll
                for (int ip = 0; ip < 4; ip++)
                    aP[ip] = *(const unsigned long long*)&As[kk][ty * 8 + ip * 2];
                float4 bv = *(const float4*)&Bs[kk][tx * 4];
                unsigned long long b0 = pack2(bv.x, bv.x);
                unsigned long long b1 = pack2(bv.y, bv.y);
                unsigned long long b2 = pack2(bv.z, bv.z);
                unsigned long long b3 = pack2(bv.w, bv.w);
#pragma unroll
                for (int ip = 0; ip < 4; ip++) {
                    fma2(acc[ip][0], aP[ip], b0);
                    fma2(acc[ip][1], aP[ip], b1);
                    fma2(acc[ip][2], aP[ip], b2);
                    fma2(acc[ip][3], aP[ip], b3);
                }
            }
            __syncthreads();
        }
    }

    float* o = g_part + (size_t)s * BB * 256;
    int n0 = bn + tx * 4;
#pragma unroll
    for (int ip = 0; ip < 4; ip++) {
        int m0 = bm + ty * 8 + ip * 2;
        float2 c0 = unpack2(acc[ip][0]);
        float2 c1 = unpack2(acc[ip][1]);
        float2 c2 = unpack2(acc[ip][2]);
        float2 c3 = unpack2(acc[ip][3]);
        *(float4*)&o[(size_t)m0 * 256 + n0]       = make_float4(c0.x, c1.x, c2.x, c3.x);
        *(float4*)&o[(size_t)(m0 + 1) * 256 + n0] = make_float4(c0.y, c1.y, c2.y, c3.y);
    }
}

// reduce split-K partials + bias + optional softplus
__global__ void k_reduce_bias_act(int S, int Nreal, const float* __restrict__ bias,
                                  int act, int dstSel, int M) {
    int i = blockIdx.x * blockDim.x + threadIdx.x;
    int total = M * Nreal;
    if (i >= total) return;
    int m = i / Nreal, n = i - m * Nreal;
    float v = 0.f;
    for (int s = 0; s < S; s++) v += g_part[(size_t)s * BB * 256 + (size_t)m * 256 + n];
    v += bias[n];
    if (act == 1) v = (v > 0.f) ? v + log1pf(expf(-v)) : log1pf(expf(v));
    if (dstSel == 0)      g_e1  [(size_t)m * HH + n] = v;
    else if (dstSel == 1) g_e2  [(size_t)m * HH + n] = v;
    else                  g_lin3[(size_t)m * TT + n] = v;
}

// ---------------- theta BN stats ----------------
__global__ void k_bn_stats_theta() {
    int t = blockIdx.x;
    __shared__ float ssum[256], ssq[256];
    float s = 0.f, q = 0.f;
    for (int m = threadIdx.x; m < BB; m += 256) {
        float v = g_lin3[m * TT + t];
        s += v; q += v * v;
    }
    ssum[threadIdx.x] = s; ssq[threadIdx.x] = q;
    __syncthreads();
    for (int o = 128; o > 0; o >>= 1) {
        if (threadIdx.x < o) { ssum[threadIdx.x] += ssum[threadIdx.x + o]; ssq[threadIdx.x] += ssq[threadIdx.x + o]; }
        __syncthreads();
    }
    if (threadIdx.x == 0) {
        float mean = ssum[0] / BB;
        float var  = ssq[0] / BB - mean * mean;
        g_mean3[t] = mean;
        g_rstd3[t] = rsqrtf(var + EPSV);
    }
}

// ---------------- BN + softmax + VQ: one warp per batch row ----------------
__global__ void k_vq(const float* __restrict__ gm, const float* __restrict__ bm,
                     const float* __restrict__ E) {
    __shared__ float Es[TT * TT];
    __shared__ float sS[8][TT];
    int tid = threadIdx.x, lane = tid & 31, wid = tid >> 5;
    for (int i = tid; i < TT * TT; i += 256) Es[i] = E[i];
    __syncthreads();
    int b = blockIdx.x * 8 + wid;

    int t0 = lane, t1 = lane + 32;
    bool v0 = (t0 < TT), v1 = (t1 < TT);
    float th0 = v0 ? (g_lin3[b * TT + t0] - g_mean3[t0]) * g_rstd3[t0] * gm[t0] + bm[t0] : -CUDART_INF_F;
    float th1 = v1 ? (g_lin3[b * TT + t1] - g_mean3[t1]) * g_rstd3[t1] * gm[t1] + bm[t1] : -CUDART_INF_F;

    float mx = fmaxf(th0, th1);
#pragma unroll
    for (int o = 16; o > 0; o >>= 1) mx = fmaxf(mx, __shfl_xor_sync(0xffffffffu, mx, o));

    float ex0 = v0 ? expf(th0 - mx) : 0.f;
    float ex1 = v1 ? expf(th1 - mx) : 0.f;
    float sum = ex0 + ex1;
#pragma unroll
    for (int o = 16; o > 0; o >>= 1) sum += __shfl_xor_sync(0xffffffffu, sum, o);

    float s0 = ex0 / sum, s1 = ex1 / sum;
    if (v0) { g_soft[b * TT + t0] = s0; sS[wid][t0] = s0; }
    if (v1) { g_soft[b * TT + t1] = s1; sS[wid][t1] = s1; }

    float sn = s0 * s0 + (v1 ? s1 * s1 : 0.f);
#pragma unroll
    for (int o = 16; o > 0; o >>= 1) sn += __shfl_xor_sync(0xffffffffu, sn, o);
    if (lane == 0) g_snorm[b] = sn;
    __syncwarp();

    float d0 = CUDART_INF_F, d1 = CUDART_INF_F;
    if (v0) {
        float dot = 0.f, en = 0.f;
#pragma unroll
        for (int u = 0; u < TT; u++) { float e = Es[t0 * TT + u]; dot += e * sS[wid][u]; en += e * e; }
        d0 = en - 2.f * dot;
    }
    if (v1) {
        float dot = 0.f, en = 0.f;
#pragma unroll
        for (int u = 0; u < TT; u++) { float e = Es[t1 * TT + u]; dot += e * sS[wid][u]; en += e * e; }
        d1 = en - 2.f * dot;
    }
    float bd = d0; int bj = t0;
    if (d1 < bd) { bd = d1; bj = t1; }
#pragma unroll
    for (int o = 16; o > 0; o >>= 1) {
        float ov = __shfl_xor_sync(0xffffffffu, bd, o);
        int   oi = __shfl_xor_sync(0xffffffffu, bj, o);
        if (ov < bd || (ov == bd && oi < bj)) { bd = ov; bj = oi; }
    }
    int jmin = bj;
    if (lane == 0) { g_enc[b] = jmin; atomicAdd(&g_counts[jmin], 1); }

    float df0 = v0 ? (Es[jmin * TT + t0] - s0) : 0.f;
    float df1 = v1 ? (Es[jmin * TT + t1] - s1) : 0.f;
    float el = df0 * df0 + df1 * df1;
#pragma unroll
    for (int o = 16; o > 0; o >>= 1) el += __shfl_xor_sync(0xffffffffu, el, o);
    if (lane == 0) atomicAdd(&g_acc[1], (double)el);
}

// ---------------- decoder BN ----------------
__global__ void k_decbn(const float* __restrict__ gd, const float* __restrict__ bd) {
    __shared__ float cnt[TT];
    for (int i = threadIdx.x; i < TT; i += 256) cnt[i] = (float)g_counts[i];
    __syncthreads();
    int v = blockIdx.x * 256 + threadIdx.x;
    if (v >= VV) return;
    float m = 0.f, q = 0.f;
    for (int c = 0; c < TT; c++) {
        float z = g_zc[(size_t)c * VV + v];
        m += cnt[c] * z; q += cnt[c] * z * z;
    }
    m /= BB; q /= BB;
    float rstd = rsqrtf(q - m * m + EPSV);
    float gg = gd[v], bbv = bd[v];
    for (int c = 0; c < TT; c++) {
        g_zhat[(size_t)c * VV + v] = (g_zc[(size_t)c * VV + v] - m) * rstd * gg + bbv;
    }
}

__global__ void k_lse() {
    int c = blockIdx.x;
    __shared__ float sm[256];
    const float* z = g_zhat + (size_t)c * VV;
    float mx = -CUDART_INF_F;
    for (int v = threadIdx.x; v < VV; v += 256) mx = fmaxf(mx, z[v]);
    sm[threadIdx.x] = mx; __syncthreads();
    for (int o = 128; o > 0; o >>= 1) { if (threadIdx.x < o) sm[threadIdx.x] = fmaxf(sm[threadIdx.x], sm[threadIdx.x + o]); __syncthreads(); }
    mx = sm[0]; __syncthreads();
    float s = 0.f;
    for (int v = threadIdx.x; v < VV; v += 256) s += expf(z[v] - mx);
    sm[threadIdx.x] = s; __syncthreads();
    for (int o = 128; o > 0; o >>= 1) { if (threadIdx.x < o) sm[threadIdx.x] += sm[threadIdx.x + o]; __syncthreads(); }
    if (threadIdx.x == 0) g_lse[c] = mx + logf(sm[0]);
}

// ---------------- distance GEMM + fuse epilogue (f32x2, 128x64 tiles) ----------------
__global__ void k_fuse(const float* __restrict__ bank, const float* __restrict__ Mcos,
                       const float* __restrict__ Mcoo, const int* __restrict__ idx) {
    __shared__ float As[TT][128 + 4];
    __shared__ float Bs[TT][64 + 4];
    int bm = blockIdx.x * 128, bn = blockIdx.y * 64;
    int tid = threadIdx.x;

    for (int e = tid; e < 128 * TT; e += 256) {
        int r = e / TT, kk = e - r * TT;
        As[kk][r] = g_soft[(size_t)(bm + r) * TT + kk];
    }
    for (int e = tid; e < 64 * TT; e += 256) {
        int r = e / TT, kk = e - r * TT;
        int nn = bn + r;
        Bs[kk][r] = (nn < NN) ? bank[(size_t)nn * TT + kk] : 0.f;
    }
    __syncthreads();

    int tx = tid & 15, ty = tid >> 4;
    unsigned long long acc[4][4];
#pragma unroll
    for (int i = 0; i < 4; i++)
#pragma unroll
        for (int j = 0; j < 4; j++) acc[i][j] = 0ULL;

#pragma unroll
    for (int kk = 0; kk < TT; kk++) {
        unsigned long long aP[4];
#pragma unroll
        for (int ip = 0; ip < 4; ip++)
            aP[ip] = *(const unsigned long long*)&As[kk][ty * 8 + ip * 2];
        float4 bv = *(const float4*)&Bs[kk][tx * 4];
        unsigned long long b0 = pack2(bv.x, bv.x);
        unsigned long long b1 = pack2(bv.y, bv.y);
        unsigned long long b2 = pack2(bv.z, bv.z);
        unsigned long long b3 = pack2(bv.w, bv.w);
#pragma unroll
        for (int ip = 0; ip < 4; ip++) {
            fma2(acc[ip][0], aP[ip], b0);
            fma2(acc[ip][1], aP[ip], b1);
            fma2(acc[ip][2], aP[ip], b2);
            fma2(acc[ip][3], aP[ip], b3);
        }
    }

    int n0 = bn + tx * 4;
    bool nok = (n0 + 3 < NN);
    float bn0 = 0, bn1 = 0, bn2 = 0, bn3 = 0;
    if (nok) { float4 t4 = *(const float4*)&g_banknorm[n0]; bn0 = t4.x; bn1 = t4.y; bn2 = t4.z; bn3 = t4.w; }
#pragma unroll
    for (int ip = 0; ip < 4; ip++) {
        float2 c0 = unpack2(acc[ip][0]);
        float2 c1 = unpack2(acc[ip][1]);
        float2 c2 = unpack2(acc[ip][2]);
        float2 c3 = unpack2(acc[ip][3]);
#pragma unroll
        for (int h = 0; h < 2; h++) {
            int m = bm + ty * 8 + ip * 2 + h;
            float dd0 = h ? c0.y : c0.x;
            float dd1 = h ? c1.y : c1.x;
            float dd2 = h ? c2.y : c2.x;
            float dd3 = h ? c3.y : c3.x;
            int ib = idx[m];
            float sn = g_snorm[m];
            size_t cbase = (size_t)ib * NN;
            if (nok) {
                float4 mc = *(const float4*)&Mcos[cbase + n0];
                float4 mo = *(const float4*)&Mcoo[cbase + n0];
                float cost, tdd, bow;
                float4 fo;
                cost = sn + bn0 - 2.f * dd0; tdd = cost * cost;
                bow = c_RHO * mc.x + (1.f - c_RHO) * mo.x;
                fo.x = (n0     == ib) ? CUDART_INF_F : c_ETA * tdd + (1.f - c_ETA) * bow;
                cost = sn + bn1 - 2.f * dd1; tdd = cost * cost;
                bow = c_RHO * mc.y + (1.f - c_RHO) * mo.y;
                fo.y = (n0 + 1 == ib) ? CUDART_INF_F : c_ETA * tdd + (1.f - c_ETA) * bow;
                cost = sn + bn2 - 2.f * dd2; tdd = cost * cost;
                bow = c_RHO * mc.z + (1.f - c_RHO) * mo.z;
                fo.z = (n0 + 2 == ib) ? CUDART_INF_F : c_ETA * tdd + (1.f - c_ETA) * bow;
                cost = sn + bn3 - 2.f * dd3; tdd = cost * cost;
                bow = c_RHO * mc.w + (1.f - c_RHO) * mo.w;
                fo.w = (n0 + 3 == ib) ? CUDART_INF_F : c_ETA * tdd + (1.f - c_ETA) * bow;
                *(float4*)&g_fuse[(size_t)m * NN + n0] = fo;
            } else {
                float dds[4] = {dd0, dd1, dd2, dd3};
#pragma unroll
                for (int j = 0; j < 4; j++) {
                    int n = n0 + j;
                    if (n < NN) {
                        float cost = sn + g_banknorm[n] - 2.f * dds[j];
                        float tdd = cost * cost;
                        float bow = c_RHO * Mcos[cbase + n] + (1.f - c_RHO) * Mcoo[cbase + n];
                        float f = (n == ib) ? CUDART_INF_F : c_ETA * tdd + (1.f - c_ETA) * bow;
                        g_fuse[(size_t)m * NN + n] = f;
                    }
                }
            }
        }
    }
}

// ---------------- top-K via exact radix-select (values are all >= 0) ----------------
// Finds the exact 32-bit key of the 20th-smallest per row, then scatters the
// top-K SET directly into the g_w code-histogram (order irrelevant downstream).
__global__ void k_topk(const int* __restrict__ is_aug) {
    int b = blockIdx.x;
    const float* row = g_fuse + (size_t)b * NN;
    int tid = threadIdx.x;
    __shared__ unsigned hist[2048];
    __shared__ unsigned scanbuf[256];
    __shared__ unsigned s_prefix, s_need;
    __shared__ int s_cnt;
    if (tid == 0) { s_prefix = 0; s_need = KK; s_cnt = 0; }
    __syncthreads();

    // 3 rounds: bits [31:21], [20:10], [9:0]
    for (int r = 0; r < 3; r++) {
        for (int i = tid; i < 2048; i += 256) hist[i] = 0;
        __syncthreads();
        unsigned pfx = s_prefix;
        for (int n4 = tid * 4; n4 < NN; n4 += 1024) {
            float4 x = *(const float4*)(row + n4);
            unsigned k4[4] = {__float_as_uint(x.x), __float_as_uint(x.y),
                              __float_as_uint(x.z), __float_as_uint(x.w)};
#pragma unroll
            for (int j = 0; j < 4; j++) {
                unsigned key = k4[j];
                if (r == 0) {
                    atomicAdd(&hist[key >> 21], 1u);
                } else if (r == 1) {
                    if ((key >> 21) == pfx) atomicAdd(&hist[(key >> 10) & 2047u], 1u);
                } else {
                    if ((key >> 10) == pfx) atomicAdd(&hist[key & 1023u], 1u);
                }
            }
        }
        __syncthreads();
        unsigned local = 0;
#pragma unroll
        for (int i = 0; i < 8; i++) local += hist[tid * 8 + i];
        scanbuf[tid] = local;
        __syncthreads();
        for (int o = 1; o < 256; o <<= 1) {
            unsigned v = (tid >= o) ? scanbuf[tid - o] : 0u;
            __syncthreads();
            scanbuf[tid] += v;
            __syncthreads();
        }
        unsigned incl = scanbuf[tid];
        unsigned excl = incl - local;
        unsigned need = s_need;
        if (excl < need && need <= incl) {
            unsigned cum = excl;
#pragma unroll
            for (int i = 0; i < 8; i++) {
                unsigned h = hist[tid * 8 + i];
                if (cum < need && need <= cum + h) {
                    unsigned bsel = (unsigned)(tid * 8 + i);
                    unsigned opfx = s_prefix;
                    s_prefix = (r == 0) ? bsel
                             : (r == 1) ? ((opfx << 11) | bsel)
                                        : ((opfx << 10) | bsel);
                    s_need = need - cum;
                    break;
                }
                cum += h;
            }
        }
        __syncthreads();
    }

    unsigned T = s_prefix;          // exact key of the K-th smallest
    unsigned need = s_need;         // how many ties at T to take (smallest index first)
    int aug = is_aug[0];
    int e = g_enc[b];

    // collection pass: strict-less -> in set; equal -> candidate buffer (reuse hist)
    for (int n4 = tid * 4; n4 < NN; n4 += 1024) {
        float4 x = *(const float4*)(row + n4);
        unsigned k4[4] = {__float_as_uint(x.x), __float_as_uint(x.y),
                          __float_as_uint(x.z), __float_as_uint(x.w)};
#pragma unroll
        for (int j = 0; j < 4; j++) {
            unsigned key = k4[j];
            int n = n4 + j;
            if (key < T) {
                if (aug) { atomicAdd(&g_w[n * 64 + e], 1); g_used[n] = 1; }
            } else if (key == T) {
                int p = atomicAdd(&s_cnt, 1);
                if (p < 2048) hist[p] = (unsigned)n;
            }
        }
    }
    __syncthreads();
    int cnt = min(s_cnt, 2048);
    if (aug) {
        // take the `need` smallest indices among the ties
        for (int i = tid; i < cnt; i += 256) {
            unsigned my = hist[i];
            int rank = 0;
            for (int j = 0; j < cnt; j++) rank += (hist[j] < my);
            if (rank < (int)need) { atomicAdd(&g_w[my * 64 + e], 1); g_used[my] = 1; }
        }
    }
}

// ---------------- per-unique-row rec contribution ----------------
__global__ void k_recrows(const float* __restrict__ training, const int* __restrict__ is_aug) {
    if (is_aug[0] == 0) return;
    int n = blockIdx.x;
    if (!g_used[n]) return;
    __shared__ float trS[VV];
    __shared__ int codes[64];
    __shared__ int wts[64];
    __shared__ int s_nc;
    __shared__ float red[256];
    __shared__ float s_S;
    __shared__ double warpc[8];
    int tid = threadIdx.x, lane = tid & 31, wid = tid >> 5;
    if (tid == 0) s_nc = 0;
    if (tid < 8) warpc[tid] = 0.0;
    __syncthreads();
    if (tid < 64) {
        int w = g_w[n * 64 + tid];
        if (w > 0) { int pp = atomicAdd(&s_nc, 1); codes[pp] = tid; wts[pp] = w; }
    }
    const float* tr = training + (size_t)n * VV;
    float sloc = 0.f;
    for (int v = tid * 4; v < VV; v += 256 * 4) {
        float4 x = *(const float4*)(tr + v);
        *(float4*)&trS[v] = x;
        sloc += x.x + x.y + x.z + x.w;
    }
    red[tid] = sloc; __syncthreads();
    for (int o = 128; o > 0; o >>= 1) { if (tid < o) red[tid] += red[tid + o]; __syncthreads(); }
    if (tid == 0) s_S = red[0];
    __syncthreads();

    int nc = s_nc;
    float S = s_S;
    for (int ci = wid; ci < nc; ci += 8) {
        int c = codes[ci];
        const float* z = g_zhat + (size_t)c * VV;
        float d = 0.f;
        for (int v = lane * 4; v < VV; v += 128) {
            float4 x = *(const float4*)&trS[v];
            float4 zz = *(const float4*)(z + v);
            d += x.x * zz.x + x.y * zz.y + x.z * zz.z + x.w * zz.w;
        }
#pragma unroll
        for (int o = 16; o > 0; o >>= 1) d += __shfl_xor_sync(0xffffffffu, d, o);
        if (lane == 0) warpc[wid] += (double)wts[ci] * ((double)g_lse[c] * (double)S - (double)d);
    }
    __syncthreads();
    if (tid == 0) {
        double contrib = 0.0;
#pragma unroll
        for (int w = 0; w < 8; w++) contrib += warpc[w];
        if (nc > 0) atomicAdd(&g_acc[0], contrib * (double)(ALPHAV / (float)KK));
    }
}

// ---------------- inputs part of rec loss ----------------
__global__ void k_recinput(const float* __restrict__ inputs) {
    int b = blockIdx.x;
    int e = g_enc[b];
    const float* z  = g_zhat + (size_t)e * VV;
    const float* xr = inputs + (size_t)b * VV;
    int tid = threadIdx.x;
    float dotI = 0.f, sumI = 0.f;
    for (int v = tid * 4; v < VV; v += 256 * 4) {
        float4 x = *(const float4*)(xr + v);
        float4 zz = *(const float4*)(z + v);
        dotI += x.x * zz.x + x.y * zz.y + x.z * zz.z + x.w * zz.w;
        sumI += x.x + x.y + x.z + x.w;
    }
    __shared__ float r1[256], r2[256];
    r1[tid] = dotI; r2[tid] = sumI;
    __syncthreads();
    for (int o = 128; o > 0; o >>= 1) {
        if (tid < o) { r1[tid] += r1[tid + o]; r2[tid] += r2[tid + o]; }
        __syncthreads();
    }
    if (tid == 0) {
        double contrib = (double)g_lse[e] * (double)r2[0] - (double)r1[0];
        atomicAdd(&g_acc[0], contrib);
    }
}

// ---------------- final ----------------
__global__ void k_final(float* out) {
    if (threadIdx.x == 0) {
        double rec = g_acc[0] / (double)BB;
        double ql  = (1.0 + (double)CCV) * (g_acc[1] / (double)(BB * TT));
        out[0] = (float)(rec + ql);
    }
}

// ---------------- launch ----------------
extern "C" void kernel_launch(void* const* d_in, const int* in_sizes, int n_in,
                              void* d_out, int out_size) {
    const int*   idx      = (const int*)  d_in[0];
    const float* inputs   = (const float*)d_in[1];
    const int*   is_aug   = (const int*)  d_in[2];
    const float* training = (const float*)d_in[3];
    const float* Mcos     = (const float*)d_in[4];
    const float* Mcoo     = (const float*)d_in[5];
    const float* bank     = (const float*)d_in[6];
    const float* W11      = (const float*)d_in[7];
    const float* b11      = (const float*)d_in[8];
    const float* W12      = (const float*)d_in[9];
    const float* b12      = (const float*)d_in[10];
    const float* W21      = (const float*)d_in[11];
    const float* b21      = (const float*)d_in[12];
    const float* gm       = (const float*)d_in[13];
    const float* bm       = (const float*)d_in[14];
    const float* gd       = (const float*)d_in[15];
    const float* bd       = (const float*)d_in[16];
    const float* Wd       = (const float*)d_in[17];
    const float* E        = (const float*)d_in[18];
    float* out = (float*)d_out;

    k_setup<<<(NN * 64 + 255) / 256, 256>>>();
    k_zc<<<(VV + 127) / 128, 128>>>(Wd, E);
    k_banknorm<<<(NN + 127) / 128, 256>>>(bank);

    // launch 4 (ncu-captured): encoder layer 1 (f32x2), split-K=16
    k_gemm_f32x2<<<dim3(8, 4, 16), 256>>>(inputs, W11, BB, HH, VV, VV, VV, 0);
    k_reduce_bias_act<<<(BB * HH + 255) / 256, 256>>>(16, HH, b11, 1, 0, BB);

    // encoder layer 2
    k_gemm_f32x2<<<dim3(8, 4, 4), 256>>>(nullptr, W12, BB, HH, HH, HH, HH, 1);
    k_reduce_bias_act<<<(BB * HH + 255) / 256, 256>>>(4, HH, b12, 1, 1, BB);

    // theta linear
    k_gemm_f32x2<<<dim3(8, 1, 4), 256>>>(nullptr, W21, BB, TT, HH, HH, HH, 2);
    k_reduce_bias_act<<<(BB * TT + 255) / 256, 256>>>(4, TT, b21, 0, 2, BB);

    // BN stats + VQ (warp-per-row)
    k_bn_stats_theta<<<TT, 256>>>();
    k_vq<<<BB / 8, 256>>>(gm, bm, E);

    // decoder per-code pipeline
    k_decbn<<<(VV + 255) / 256, 256>>>(gd, bd);
    k_lse<<<TT, 256>>>();

    // augmentation: fuse + radix-select topk (scatter fused)
    k_fuse<<<dim3(8, (NN + 63) / 64), 256>>>(bank, Mcos, Mcoo, idx);
    k_topk<<<BB, 256>>>(is_aug);

    // rec loss
    k_recrows<<<NN, 256>>>(training, is_aug);
    k_recinput<<<BB, 256>>>(inputs);
    k_final<<<1, 1>>>(out);
}

// round 14
// speedup vs baseline: 2.3904x; 1.0146x over previous
#include <cuda_runtime.h>
#include <math_constants.h>

#define BB 1024
#define VV 5000
#define NN 10000
#define TT 50
#define HH 200
#define KK 20

static __device__ __constant__ float c_ETA  = 0.5f;
static __device__ __constant__ float c_RHO  = 0.5f;
#define EPSV 1e-5f
#define CCV  0.25f
#define ALPHAV 1.0f

// ---------------- device scratch ----------------
__device__ float g_e1[BB*HH];
__device__ float g_e2[BB*HH];
__device__ float g_lin3[BB*TT];
__device__ float g_part[16*BB*256];
__device__ float g_soft[BB*TT];
__device__ float g_snorm[BB];
__device__ int   g_enc[BB];
__device__ int   g_counts[TT];
__device__ float g_mean3[TT];
__device__ float g_rstd3[TT];
__device__ float g_zc[TT*VV];
__device__ float g_zhat[TT*VV];
__device__ float g_lse[TT];
__device__ float g_banknorm[NN];
__device__ float g_fuse[(size_t)BB*NN];
__device__ int   g_w[NN*64];
__device__ int   g_used[NN];
__device__ double g_acc[2];

// ---------------- setup ----------------
__global__ void k_setup() {
    int i = blockIdx.x * 256 + threadIdx.x;
    if (i < NN * 64) g_w[i] = 0;
    if (i < NN) g_used[i] = 0;
    if (i < TT) g_counts[i] = 0;
    if (i < 2)  g_acc[i] = 0.0;
}

// ---------------- code logits (coalesced) ----------------
__global__ void k_zc(const float* __restrict__ Wd, const float* __restrict__ E) {
    __shared__ float Es[TT * TT];
    __shared__ float wS[128 * TT];
    int v0 = blockIdx.x * 128;
    for (int i = threadIdx.x; i < TT * TT; i += 128) Es[i] = E[i];
    for (int e = threadIdx.x; e < 128 * TT; e += 128) {
        int gidx = v0 * TT + e;
        wS[e] = (gidx < VV * TT) ? Wd[gidx] : 0.f;
    }
    __syncthreads();
    int v = v0 + threadIdx.x;
    if (v >= VV) return;
    float w[TT];
#pragma unroll
    for (int t = 0; t < TT; t++) w[t] = wS[threadIdx.x * TT + t];
    for (int c = 0; c < TT; c++) {
        float a = 0.f;
#pragma unroll
        for (int t = 0; t < TT; t++) a += Es[c * TT + t] * w[t];
        g_zc[(size_t)c * VV + v] = a;
    }
}

// ---------------- bank norms (coalesced) ----------------
__global__ void k_banknorm(const float* __restrict__ bank) {
    __shared__ float bS[128 * TT];
    int n0 = blockIdx.x * 128;
    for (int e = threadIdx.x; e < 128 * TT; e += 256) {
        int gidx = n0 * TT + e;
        bS[e] = (gidx < NN * TT) ? bank[gidx] : 0.f;
    }
    __syncthreads();
    if (threadIdx.x < 128) {
        int n = n0 + threadIdx.x;
        if (n < NN) {
            float s = 0.f;
#pragma unroll
            for (int t = 0; t < TT; t++) { float v = bS[threadIdx.x * TT + t]; s += v * v; }
            g_banknorm[n] = s;
        }
    }
}

// ---------------- f32x2 helpers ----------------
__device__ __forceinline__ void fma2(unsigned long long &c, unsigned long long a, unsigned long long b) {
    asm("fma.rn.f32x2 %0, %1, %2, %0;" : "+l"(c) : "l"(a), "l"(b));
}
__device__ __forceinline__ unsigned long long pack2(float x, float y) {
    unsigned long long r; asm("mov.b64 %0, {%1,%2};" : "=l"(r) : "f"(x), "f"(y));
    return r;
}
__device__ __forceinline__ float2 unpack2(unsigned long long v) {
    float2 r; asm("mov.b64 {%0,%1}, %2;" : "=f"(r.x), "=f"(r.y) : "l"(v));
    return r;
}

// ---------------- f32x2 NT GEMM: 128x128 tile, 8x8 microtile ----------------
__global__ void __launch_bounds__(256, 2)
k_gemm_f32x2(const float* __restrict__ Aext, const float* __restrict__ Bm,
             int M, int Nmat, int Kdim, int lda, int ldb, int aSel) {
    const float* A = Aext;
    if (aSel == 1) A = g_e1; else if (aSel == 2) A = g_e2;

    const int BM = 128, BN = 128, BK = 8;
    __shared__ float As[BK][BM + 4];
    __shared__ float Bs[BK][BN + 4];

    int bm = blockIdx.x * BM, bn = blockIdx.y * BN;
    int s = blockIdx.z, Sn = gridDim.z;
    int kchunk = (((Kdim + Sn - 1) / Sn) + BK - 1) & ~(BK - 1);
    int k0 = s * kchunk, k1 = min(Kdim, k0 + kchunk);

    int tid = threadIdx.x;
    int tx = tid & 15, ty = tid >> 4;          // 16 x 16 threads, each 8m x 8n
    int lrow = tid >> 1, lkq = (tid & 1) * 4;  // loaders: 128 rows x 2 threads

    unsigned long long acc[4][8];
#pragma unroll
    for (int i = 0; i < 4; i++)
#pragma unroll
        for (int j = 0; j < 8; j++) acc[i][j] = 0ULL;

    if (k0 < k1) {
        float4 ar, br;
        // first tile loads
        {
            int gk = k0 + lkq;
            const float* ap = A + (size_t)(bm + lrow) * lda + gk;
            if (bm + lrow < M && gk + 3 < k1) ar = *(const float4*)ap;
            else {
                float t[4];
#pragma unroll
                for (int i = 0; i < 4; i++)
                    t[i] = (bm + lrow < M && gk + i < k1) ? ap[i] : 0.f;
                ar = make_float4(t[0], t[1], t[2], t[3]);
            }
            int brow = bn + lrow;
            const float* bp = Bm + (size_t)brow * ldb + gk;
            if (brow < Nmat && gk + 3 < k1) br = *(const float4*)bp;
            else {
                float t[4];
#pragma unroll
                for (int i = 0; i < 4; i++)
                    t[i] = (brow < Nmat && gk + i < k1) ? bp[i] : 0.f;
                br = make_float4(t[0], t[1], t[2], t[3]);
            }
        }

        for (int kt = k0; kt < k1; kt += BK) {
            As[lkq + 0][lrow] = ar.x; As[lkq + 1][lrow] = ar.y;
            As[lkq + 2][lrow] = ar.z; As[lkq + 3][lrow] = ar.w;
            Bs[lkq + 0][lrow] = br.x; Bs[lkq + 1][lrow] = br.y;
            Bs[lkq + 2][lrow] = br.z; Bs[lkq + 3][lrow] = br.w;
            __syncthreads();

            int ktn = kt + BK;
            if (ktn < k1) {
                int gk = ktn + lkq;
                const float* ap = A + (size_t)(bm + lrow) * lda + gk;
                if (bm + lrow < M && gk + 3 < k1) ar = *(const float4*)ap;
                else {
                    float t[4];
#pragma unroll
                    for (int i = 0; i < 4; i++)
                        t[i] = (bm + lrow < M && gk + i < k1) ? ap[i] : 0.f;
                    ar = make_float4(t[0], t[1], t[2], t[3]);
                }
                int brow = bn + lrow;
                const float* bp = Bm + (size_t)brow * ldb + gk;
                if (brow < Nmat && gk + 3 < k1) br = *(const float4*)bp;
                else {
                    float t[4];
#pragma unroll
                    for (int i = 0; i < 4; i++)
                        t[i] = (brow < Nmat && gk + i < k1) ? bp[i] : 0.f;
                    br = make_float4(t[0], t[1], t[2], t[3]);
                }
            }

#pragma unroll
            for (int kk = 0; kk < BK; kk++) {
                unsigned long long aP[4];
#pragma unroll
                for (int ip = 0; ip < 4; ip++)
                    aP[ip] = *(const unsigned long long*)&As[kk][ty * 8 + ip * 2];
                float4 f0 = *(const float4*)&Bs[kk][tx * 8];
                float4 f1 = *(const float4*)&Bs[kk][tx * 8 + 4];
                unsigned long long bb[8];
                bb[0] = pack2(f0.x, f0.x); bb[1] = pack2(f0.y, f0.y);
                bb[2] = pack2(f0.z, f0.z); bb[3] = pack2(f0.w, f0.w);
                bb[4] = pack2(f1.x, f1.x); bb[5] = pack2(f1.y, f1.y);
                bb[6] = pack2(f1.z, f1.z); bb[7] = pack2(f1.w, f1.w);
#pragma unroll
                for (int ip = 0; ip < 4; ip++) {
#pragma unroll
                    for (int j = 0; j < 8; j++) fma2(acc[ip][j], aP[ip], bb[j]);
                }
            }
            __syncthreads();
        }
    }

    float* o = g_part + (size_t)s * BB * 256;
    int n0 = bn + tx * 8;
#pragma unroll
    for (int ip = 0; ip < 4; ip++) {
        float2 c[8];
#pragma unroll
        for (int j = 0; j < 8; j++) c[j] = unpack2(acc[ip][j]);
        int m0 = bm + ty * 8 + ip * 2;
        *(float4*)&o[(size_t)m0 * 256 + n0]           = make_float4(c[0].x, c[1].x, c[2].x, c[3].x);
        *(float4*)&o[(size_t)m0 * 256 + n0 + 4]       = make_float4(c[4].x, c[5].x, c[6].x, c[7].x);
        *(float4*)&o[(size_t)(m0 + 1) * 256 + n0]     = make_float4(c[0].y, c[1].y, c[2].y, c[3].y);
        *(float4*)&o[(size_t)(m0 + 1) * 256 + n0 + 4] = make_float4(c[4].y, c[5].y, c[6].y, c[7].y);
    }
}

// reduce split-K partials + bias + optional softplus
__global__ void k_reduce_bias_act(int S, int Nreal, const float* __restrict__ bias,
                                  int act, int dstSel, int M) {
    int i = blockIdx.x * blockDim.x + threadIdx.x;
    int total = M * Nreal;
    if (i >= total) return;
    int m = i / Nreal, n = i - m * Nreal;
    float v = 0.f;
    for (int s = 0; s < S; s++) v += g_part[(size_t)s * BB * 256 + (size_t)m * 256 + n];
    v += bias[n];
    if (act == 1) v = (v > 0.f) ? v + log1pf(expf(-v)) : log1pf(expf(v));
    if (dstSel == 0)      g_e1  [(size_t)m * HH + n] = v;
    else if (dstSel == 1) g_e2  [(size_t)m * HH + n] = v;
    else                  g_lin3[(size_t)m * TT + n] = v;
}

// ---------------- theta BN stats ----------------
__global__ void k_bn_stats_theta() {
    int t = blockIdx.x;
    __shared__ float ssum[256], ssq[256];
    float s = 0.f, q = 0.f;
    for (int m = threadIdx.x; m < BB; m += 256) {
        float v = g_lin3[m * TT + t];
        s += v; q += v * v;
    }
    ssum[threadIdx.x] = s; ssq[threadIdx.x] = q;
    __syncthreads();
    for (int o = 128; o > 0; o >>= 1) {
        if (threadIdx.x < o) { ssum[threadIdx.x] += ssum[threadIdx.x + o]; ssq[threadIdx.x] += ssq[threadIdx.x + o]; }
        __syncthreads();
    }
    if (threadIdx.x == 0) {
        float mean = ssum[0] / BB;
        float var  = ssq[0] / BB - mean * mean;
        g_mean3[t] = mean;
        g_rstd3[t] = rsqrtf(var + EPSV);
    }
}

// ---------------- BN + softmax + VQ: one warp per batch row ----------------
__global__ void k_vq(const float* __restrict__ gm, const float* __restrict__ bm,
                     const float* __restrict__ E) {
    __shared__ float Es[TT * TT];
    __shared__ float sS[8][TT];
    int tid = threadIdx.x, lane = tid & 31, wid = tid >> 5;
    for (int i = tid; i < TT * TT; i += 256) Es[i] = E[i];
    __syncthreads();
    int b = blockIdx.x * 8 + wid;

    int t0 = lane, t1 = lane + 32;
    bool v0 = (t0 < TT), v1 = (t1 < TT);
    float th0 = v0 ? (g_lin3[b * TT + t0] - g_mean3[t0]) * g_rstd3[t0] * gm[t0] + bm[t0] : -CUDART_INF_F;
    float th1 = v1 ? (g_lin3[b * TT + t1] - g_mean3[t1]) * g_rstd3[t1] * gm[t1] + bm[t1] : -CUDART_INF_F;

    float mx = fmaxf(th0, th1);
#pragma unroll
    for (int o = 16; o > 0; o >>= 1) mx = fmaxf(mx, __shfl_xor_sync(0xffffffffu, mx, o));

    float ex0 = v0 ? expf(th0 - mx) : 0.f;
    float ex1 = v1 ? expf(th1 - mx) : 0.f;
    float sum = ex0 + ex1;
#pragma unroll
    for (int o = 16; o > 0; o >>= 1) sum += __shfl_xor_sync(0xffffffffu, sum, o);

    float s0 = ex0 / sum, s1 = ex1 / sum;
    if (v0) { g_soft[b * TT + t0] = s0; sS[wid][t0] = s0; }
    if (v1) { g_soft[b * TT + t1] = s1; sS[wid][t1] = s1; }

    float sn = s0 * s0 + (v1 ? s1 * s1 : 0.f);
#pragma unroll
    for (int o = 16; o > 0; o >>= 1) sn += __shfl_xor_sync(0xffffffffu, sn, o);
    if (lane == 0) g_snorm[b] = sn;
    __syncwarp();

    float d0 = CUDART_INF_F, d1 = CUDART_INF_F;
    if (v0) {
        float dot = 0.f, en = 0.f;
#pragma unroll
        for (int u = 0; u < TT; u++) { float e = Es[t0 * TT + u]; dot += e * sS[wid][u]; en += e * e; }
        d0 = en - 2.f * dot;
    }
    if (v1) {
        float dot = 0.f, en = 0.f;
#pragma unroll
        for (int u = 0; u < TT; u++) { float e = Es[t1 * TT + u]; dot += e * sS[wid][u]; en += e * e; }
        d1 = en - 2.f * dot;
    }
    float bd = d0; int bj = t0;
    if (d1 < bd) { bd = d1; bj = t1; }
#pragma unroll
    for (int o = 16; o > 0; o >>= 1) {
        float ov = __shfl_xor_sync(0xffffffffu, bd, o);
        int   oi = __shfl_xor_sync(0xffffffffu, bj, o);
        if (ov < bd || (ov == bd && oi < bj)) { bd = ov; bj = oi; }
    }
    int jmin = bj;
    if (lane == 0) { g_enc[b] = jmin; atomicAdd(&g_counts[jmin], 1); }

    float df0 = v0 ? (Es[jmin * TT + t0] - s0) : 0.f;
    float df1 = v1 ? (Es[jmin * TT + t1] - s1) : 0.f;
    float el = df0 * df0 + df1 * df1;
#pragma unroll
    for (int o = 16; o > 0; o >>= 1) el += __shfl_xor_sync(0xffffffffu, el, o);
    if (lane == 0) atomicAdd(&g_acc[1], (double)el);
}

// ---------------- decoder BN ----------------
__global__ void k_decbn(const float* __restrict__ gd, const float* __restrict__ bd) {
    __shared__ float cnt[TT];
    for (int i = threadIdx.x; i < TT; i += 256) cnt[i] = (float)g_counts[i];
    __syncthreads();
    int v = blockIdx.x * 256 + threadIdx.x;
    if (v >= VV) return;
    float m = 0.f, q = 0.f;
    for (int c = 0; c < TT; c++) {
        float z = g_zc[(size_t)c * VV + v];
        m += cnt[c] * z; q += cnt[c] * z * z;
    }
    m /= BB; q /= BB;
    float rstd = rsqrtf(q - m * m + EPSV);
    float gg = gd[v], bbv = bd[v];
    for (int c = 0; c < TT; c++) {
        g_zhat[(size_t)c * VV + v] = (g_zc[(size_t)c * VV + v] - m) * rstd * gg + bbv;
    }
}

__global__ void k_lse() {
    int c = blockIdx.x;
    __shared__ float sm[256];
    const float* z = g_zhat + (size_t)c * VV;
    float mx = -CUDART_INF_F;
    for (int v = threadIdx.x; v < VV; v += 256) mx = fmaxf(mx, z[v]);
    sm[threadIdx.x] = mx; __syncthreads();
    for (int o = 128; o > 0; o >>= 1) { if (threadIdx.x < o) sm[threadIdx.x] = fmaxf(sm[threadIdx.x], sm[threadIdx.x + o]); __syncthreads(); }
    mx = sm[0]; __syncthreads();
    float s = 0.f;
    for (int v = threadIdx.x; v < VV; v += 256) s += expf(z[v] - mx);
    sm[threadIdx.x] = s; __syncthreads();
    for (int o = 128; o > 0; o >>= 1) { if (threadIdx.x < o) sm[threadIdx.x] += sm[threadIdx.x + o]; __syncthreads(); }
    if (threadIdx.x == 0) g_lse[c] = mx + logf(sm[0]);
}

// ---------------- distance GEMM + fuse epilogue (f32x2, 128x64 tiles) ----------------
__global__ void k_fuse(const float* __restrict__ bank, const float* __restrict__ Mcos,
                       const float* __restrict__ Mcoo, const int* __restrict__ idx) {
    __shared__ float As[TT][128 + 4];
    __shared__ float Bs[TT][64 + 4];
    int bm = blockIdx.x * 128, bn = blockIdx.y * 64;
    int tid = threadIdx.x;

    for (int e = tid; e < 128 * TT; e += 256) {
        int r = e / TT, kk = e - r * TT;
        As[kk][r] = g_soft[(size_t)(bm + r) * TT + kk];
    }
    for (int e = tid; e < 64 * TT; e += 256) {
        int r = e / TT, kk = e - r * TT;
        int nn = bn + r;
        Bs[kk][r] = (nn < NN) ? bank[(size_t)nn * TT + kk] : 0.f;
    }
    __syncthreads();

    int tx = tid & 15, ty = tid >> 4;
    unsigned long long acc[4][4];
#pragma unroll
    for (int i = 0; i < 4; i++)
#pragma unroll
        for (int j = 0; j < 4; j++) acc[i][j] = 0ULL;

#pragma unroll
    for (int kk = 0; kk < TT; kk++) {
        unsigned long long aP[4];
#pragma unroll
        for (int ip = 0; ip < 4; ip++)
            aP[ip] = *(const unsigned long long*)&As[kk][ty * 8 + ip * 2];
        float4 bv = *(const float4*)&Bs[kk][tx * 4];
        unsigned long long b0 = pack2(bv.x, bv.x);
        unsigned long long b1 = pack2(bv.y, bv.y);
        unsigned long long b2 = pack2(bv.z, bv.z);
        unsigned long long b3 = pack2(bv.w, bv.w);
#pragma unroll
        for (int ip = 0; ip < 4; ip++) {
            fma2(acc[ip][0], aP[ip], b0);
            fma2(acc[ip][1], aP[ip], b1);
            fma2(acc[ip][2], aP[ip], b2);
            fma2(acc[ip][3], aP[ip], b3);
        }
    }

    int n0 = bn + tx * 4;
    bool nok = (n0 + 3 < NN);
    float bn0 = 0, bn1 = 0, bn2 = 0, bn3 = 0;
    if (nok) { float4 t4 = *(const float4*)&g_banknorm[n0]; bn0 = t4.x; bn1 = t4.y; bn2 = t4.z; bn3 = t4.w; }
#pragma unroll
    for (int ip = 0; ip < 4; ip++) {
        float2 c0 = unpack2(acc[ip][0]);
        float2 c1 = unpack2(acc[ip][1]);
        float2 c2 = unpack2(acc[ip][2]);
        float2 c3 = unpack2(acc[ip][3]);
#pragma unroll
        for (int h = 0; h < 2; h++) {
            int m = bm + ty * 8 + ip * 2 + h;
            float dd0 = h ? c0.y : c0.x;
            float dd1 = h ? c1.y : c1.x;
            float dd2 = h ? c2.y : c2.x;
            float dd3 = h ? c3.y : c3.x;
            int ib = idx[m];
            float sn = g_snorm[m];
            size_t cbase = (size_t)ib * NN;
            if (nok) {
                float4 mc = *(const float4*)&Mcos[cbase + n0];
                float4 mo = *(const float4*)&Mcoo[cbase + n0];
                float cost, tdd, bow;
                float4 fo;
                cost = sn + bn0 - 2.f * dd0; tdd = cost * cost;
                bow = c_RHO * mc.x + (1.f - c_RHO) * mo.x;
                fo.x = (n0     == ib) ? CUDART_INF_F : c_ETA * tdd + (1.f - c_ETA) * bow;
                cost = sn + bn1 - 2.f * dd1; tdd = cost * cost;
                bow = c_RHO * mc.y + (1.f - c_RHO) * mo.y;
                fo.y = (n0 + 1 == ib) ? CUDART_INF_F : c_ETA * tdd + (1.f - c_ETA) * bow;
                cost = sn + bn2 - 2.f * dd2; tdd = cost * cost;
                bow = c_RHO * mc.z + (1.f - c_RHO) * mo.z;
                fo.z = (n0 + 2 == ib) ? CUDART_INF_F : c_ETA * tdd + (1.f - c_ETA) * bow;
                cost = sn + bn3 - 2.f * dd3; tdd = cost * cost;
                bow = c_RHO * mc.w + (1.f - c_RHO) * mo.w;
                fo.w = (n0 + 3 == ib) ? CUDART_INF_F : c_ETA * tdd + (1.f - c_ETA) * bow;
                *(float4*)&g_fuse[(size_t)m * NN + n0] = fo;
            } else {
                float dds[4] = {dd0, dd1, dd2, dd3};
#pragma unroll
                for (int j = 0; j < 4; j++) {
                    int n = n0 + j;
                    if (n < NN) {
                        float cost = sn + g_banknorm[n] - 2.f * dds[j];
                        float tdd = cost * cost;
                        float bow = c_RHO * Mcos[cbase + n] + (1.f - c_RHO) * Mcoo[cbase + n];
                        float f = (n == ib) ? CUDART_INF_F : c_ETA * tdd + (1.f - c_ETA) * bow;
                        g_fuse[(size_t)m * NN + n] = f;
                    }
                }
            }
        }
    }
}

// ---------------- top-K via exact radix-select ----------------
__global__ void k_topk(const int* __restrict__ is_aug) {
    int b = blockIdx.x;
    const float* row = g_fuse + (size_t)b * NN;
    int tid = threadIdx.x;
    __shared__ unsigned hist[2048];
    __shared__ unsigned scanbuf[256];
    __shared__ unsigned s_prefix, s_need;
    __shared__ int s_cnt;
    if (tid == 0) { s_prefix = 0; s_need = KK; s_cnt = 0; }
    __syncthreads();

    for (int r = 0; r < 3; r++) {
        for (int i = tid; i < 2048; i += 256) hist[i] = 0;
        __syncthreads();
        unsigned pfx = s_prefix;
        for (int n4 = tid * 4; n4 < NN; n4 += 1024) {
            float4 x = *(const float4*)(row + n4);
            unsigned k4[4] = {__float_as_uint(x.x), __float_as_uint(x.y),
                              __float_as_uint(x.z), __float_as_uint(x.w)};
#pragma unroll
            for (int j = 0; j < 4; j++) {
                unsigned key = k4[j];
                if (r == 0) {
                    atomicAdd(&hist[key >> 21], 1u);
                } else if (r == 1) {
                    if ((key >> 21) == pfx) atomicAdd(&hist[(key >> 10) & 2047u], 1u);
                } else {
                    if ((key >> 10) == pfx) atomicAdd(&hist[key & 1023u], 1u);
                }
            }
        }
        __syncthreads();
        unsigned local = 0;
#pragma unroll
        for (int i = 0; i < 8; i++) local += hist[tid * 8 + i];
        scanbuf[tid] = local;
        __syncthreads();
        for (int o = 1; o < 256; o <<= 1) {
            unsigned v = (tid >= o) ? scanbuf[tid - o] : 0u;
            __syncthreads();
            scanbuf[tid] += v;
            __syncthreads();
        }
        unsigned incl = scanbuf[tid];
        unsigned excl = incl - local;
        unsigned need = s_need;
        if (excl < need && need <= incl) {
            unsigned cum = excl;
#pragma unroll
            for (int i = 0; i < 8; i++) {
                unsigned h = hist[tid * 8 + i];
                if (cum < need && need <= cum + h) {
                    unsigned bsel = (unsigned)(tid * 8 + i);
                    unsigned opfx = s_prefix;
                    s_prefix = (r == 0) ? bsel
                             : (r == 1) ? ((opfx << 11) | bsel)
                                        : ((opfx << 10) | bsel);
                    s_need = need - cum;
                    break;
                }
                cum += h;
            }
        }
        __syncthreads();
    }

    unsigned T = s_prefix;
    unsigned need = s_need;
    int aug = is_aug[0];
    int e = g_enc[b];

    for (int n4 = tid * 4; n4 < NN; n4 += 1024) {
        float4 x = *(const float4*)(row + n4);
        unsigned k4[4] = {__float_as_uint(x.x), __float_as_uint(x.y),
                          __float_as_uint(x.z), __float_as_uint(x.w)};
#pragma unroll
        for (int j = 0; j < 4; j++) {
            unsigned key = k4[j];
            int n = n4 + j;
            if (key < T) {
                if (aug) { atomicAdd(&g_w[n * 64 + e], 1); g_used[n] = 1; }
            } else if (key == T) {
                int p = atomicAdd(&s_cnt, 1);
                if (p < 2048) hist[p] = (unsigned)n;
            }
        }
    }
    __syncthreads();
    int cnt = min(s_cnt, 2048);
    if (aug) {
        for (int i = tid; i < cnt; i += 256) {
            unsigned my = hist[i];
            int rank = 0;
            for (int j = 0; j < cnt; j++) rank += (hist[j] < my);
            if (rank < (int)need) { atomicAdd(&g_w[my * 64 + e], 1); g_used[my] = 1; }
        }
    }
}

// ---------------- rec loss: merged rows + inputs kernel ----------------
__global__ void k_rec(const float* __restrict__ training, const float* __restrict__ inputs,
                      const int* __restrict__ is_aug) {
    int blk = blockIdx.x;
    int tid = threadIdx.x, lane = tid & 31, wid = tid >> 5;

    if (blk >= NN) {
        // inputs part: b = blk - NN
        int b = blk - NN;
        int e = g_enc[b];
        const float* z  = g_zhat + (size_t)e * VV;
        const float* xr = inputs + (size_t)b * VV;
        float dotI = 0.f, sumI = 0.f;
        for (int v = tid * 4; v < VV; v += 256 * 4) {
            float4 x = *(const float4*)(xr + v);
            float4 zz = *(const float4*)(z + v);
            dotI += x.x * zz.x + x.y * zz.y + x.z * zz.z + x.w * zz.w;
            sumI += x.x + x.y + x.z + x.w;
        }
        __shared__ float r1[256], r2[256];
        r1[tid] = dotI; r2[tid] = sumI;
        __syncthreads();
        for (int o = 128; o > 0; o >>= 1) {
            if (tid < o) { r1[tid] += r1[tid + o]; r2[tid] += r2[tid + o]; }
            __syncthreads();
        }
        if (tid == 0) {
            double contrib = (double)g_lse[e] * (double)r2[0] - (double)r1[0];
            atomicAdd(&g_acc[0], contrib);
        }
        return;
    }

    // training-row part
    if (is_aug[0] == 0) return;
    int n = blk;
    if (!g_used[n]) return;
    __shared__ float trS[VV];
    __shared__ int codes[64];
    __shared__ int wts[64];
    __shared__ int s_nc;
    __shared__ float red[256];
    __shared__ float s_S;
    __shared__ double warpc[8];
    if (tid == 0) s_nc = 0;
    if (tid < 8) warpc[tid] = 0.0;
    __syncthreads();
    if (tid < 64) {
        int w = g_w[n * 64 + tid];
        if (w > 0) { int pp = atomicAdd(&s_nc, 1); codes[pp] = tid; wts[pp] = w; }
    }
    const float* tr = training + (size_t)n * VV;
    float sloc = 0.f;
    for (int v = tid * 4; v < VV; v += 256 * 4) {
        float4 x = *(const float4*)(tr + v);
        *(float4*)&trS[v] = x;
        sloc += x.x + x.y + x.z + x.w;
    }
    red[tid] = sloc; __syncthreads();
    for (int o = 128; o > 0; o >>= 1) { if (tid < o) red[tid] += red[tid + o]; __syncthreads(); }
    if (tid == 0) s_S = red[0];
    __syncthreads();

    int nc = s_nc;
    float S = s_S;
    for (int ci = wid; ci < nc; ci += 8) {
        int c = codes[ci];
        const float* z = g_zhat + (size_t)c * VV;
        float d = 0.f;
        for (int v = lane * 4; v < VV; v += 128) {
            float4 x = *(const float4*)&trS[v];
            float4 zz = *(const float4*)(z + v);
            d += x.x * zz.x + x.y * zz.y + x.z * zz.z + x.w * zz.w;
        }
#pragma unroll
        for (int o = 16; o > 0; o >>= 1) d += __shfl_xor_sync(0xffffffffu, d, o);
        if (lane == 0) warpc[wid] += (double)wts[ci] * ((double)g_lse[c] * (double)S - (double)d);
    }
    __syncthreads();
    if (tid == 0) {
        double contrib = 0.0;
#pragma unroll
        for (int w = 0; w < 8; w++) contrib += warpc[w];
        if (nc > 0) atomicAdd(&g_acc[0], contrib * (double)(ALPHAV / (float)KK));
    }
}

// ---------------- final ----------------
__global__ void k_final(float* out) {
    if (threadIdx.x == 0) {
        double rec = g_acc[0] / (double)BB;
        double ql  = (1.0 + (double)CCV) * (g_acc[1] / (double)(BB * TT));
        out[0] = (float)(rec + ql);
    }
}

// ---------------- launch ----------------
extern "C" void kernel_launch(void* const* d_in, const int* in_sizes, int n_in,
                              void* d_out, int out_size) {
    const int*   idx      = (const int*)  d_in[0];
    const float* inputs   = (const float*)d_in[1];
    const int*   is_aug   = (const int*)  d_in[2];
    const float* training = (const float*)d_in[3];
    const float* Mcos     = (const float*)d_in[4];
    const float* Mcoo     = (const float*)d_in[5];
    const float* bank     = (const float*)d_in[6];
    const float* W11      = (const float*)d_in[7];
    const float* b11      = (const float*)d_in[8];
    const float* W12      = (const float*)d_in[9];
    const float* b12      = (const float*)d_in[10];
    const float* W21      = (const float*)d_in[11];
    const float* b21      = (const float*)d_in[12];
    const float* gm       = (const float*)d_in[13];
    const float* bm       = (const float*)d_in[14];
    const float* gd       = (const float*)d_in[15];
    const float* bd       = (const float*)d_in[16];
    const float* Wd       = (const float*)d_in[17];
    const float* E        = (const float*)d_in[18];
    float* out = (float*)d_out;

    k_setup<<<(NN * 64 + 255) / 256, 256>>>();
    k_zc<<<(VV + 127) / 128, 128>>>(Wd, E);
    k_banknorm<<<(NN + 127) / 128, 256>>>(bank);

    // launch 4 (ncu-captured): encoder layer 1, 8x8 microtile, split-K=16
    k_gemm_f32x2<<<dim3(8, 2, 16), 256>>>(inputs, W11, BB, HH, VV, VV, VV, 0);
    k_reduce_bias_act<<<(BB * HH + 255) / 256, 256>>>(16, HH, b11, 1, 0, BB);

    // encoder layer 2
    k_gemm_f32x2<<<dim3(8, 2, 8), 256>>>(nullptr, W12, BB, HH, HH, HH, HH, 1);
    k_reduce_bias_act<<<(BB * HH + 255) / 256, 256>>>(8, HH, b12, 1, 1, BB);

    // theta linear (N=50 -> single column block)
    k_gemm_f32x2<<<dim3(8, 1, 8), 256>>>(nullptr, W21, BB, TT, HH, HH, HH, 2);
    k_reduce_bias_act<<<(BB * TT + 255) / 256, 256>>>(8, TT, b21, 0, 2, BB);

    // BN stats + VQ
    k_bn_stats_theta<<<TT, 256>>>();
    k_vq<<<BB / 8, 256>>>(gm, bm, E);

    // decoder per-code pipeline
    k_decbn<<<(VV + 255) / 256, 256>>>(gd, bd);
    k_lse<<<TT, 256>>>();

    // augmentation: fuse + radix-select topk
    k_fuse<<<dim3(8, (NN + 63) / 64), 256>>>(bank, Mcos, Mcoo, idx);
    k_topk<<<BB, 256>>>(is_aug);

    // rec loss (merged rows + inputs)
    k_rec<<<NN + BB, 256>>>(training, inputs, is_aug);
    k_final<<<1, 1>>>(out);
}

// round 17
// speedup vs baseline: 2.5524x; 1.0678x over previous
#include <cuda_runtime.h>
#include <math_constants.h>

#define BB 1024
#define VV 5000
#define NN 10000
#define TT 50
#define HH 200
#define KK 20

static __device__ __constant__ float c_ETA  = 0.5f;
static __device__ __constant__ float c_RHO  = 0.5f;
#define EPSV 1e-5f
#define CCV  0.25f
#define ALPHAV 1.0f

// ---------------- device scratch ----------------
__device__ float g_e1[BB*HH];
__device__ float g_e2[BB*HH];
__device__ float g_lin3[BB*TT];
__device__ float g_part[24*BB*256];
__device__ float g_soft[BB*TT];
__device__ float g_snorm[BB];
__device__ int   g_enc[BB];
__device__ int   g_counts[TT];
__device__ float g_mean3[TT];
__device__ float g_rstd3[TT];
__device__ float g_zc[TT*VV];
__device__ float g_zhat[TT*VV];
__device__ float g_lse[TT];
__device__ float g_banknorm[NN];
__device__ float g_fuse[(size_t)BB*NN];
__device__ int   g_w[NN*64];
__device__ int   g_used[NN];
__device__ double g_acc[2];

// ---------------- setup ----------------
__global__ void k_setup() {
    int i = blockIdx.x * 256 + threadIdx.x;
    if (i < NN * 64) g_w[i] = 0;
    if (i < NN) g_used[i] = 0;
    if (i < TT) g_counts[i] = 0;
    if (i < 2)  g_acc[i] = 0.0;
}

// ---------------- code logits (coalesced) ----------------
__global__ void k_zc(const float* __restrict__ Wd, const float* __restrict__ E) {
    __shared__ float Es[TT * TT];
    __shared__ float wS[128 * TT];
    int v0 = blockIdx.x * 128;
    for (int i = threadIdx.x; i < TT * TT; i += 128) Es[i] = E[i];
    for (int e = threadIdx.x; e < 128 * TT; e += 128) {
        int gidx = v0 * TT + e;
        wS[e] = (gidx < VV * TT) ? Wd[gidx] : 0.f;
    }
    __syncthreads();
    int v = v0 + threadIdx.x;
    if (v >= VV) return;
    float w[TT];
#pragma unroll
    for (int t = 0; t < TT; t++) w[t] = wS[threadIdx.x * TT + t];
    for (int c = 0; c < TT; c++) {
        float a = 0.f;
#pragma unroll
        for (int t = 0; t < TT; t++) a += Es[c * TT + t] * w[t];
        g_zc[(size_t)c * VV + v] = a;
    }
}

// ---------------- bank norms (coalesced) ----------------
__global__ void k_banknorm(const float* __restrict__ bank) {
    __shared__ float bS[128 * TT];
    int n0 = blockIdx.x * 128;
    for (int e = threadIdx.x; e < 128 * TT; e += 256) {
        int gidx = n0 * TT + e;
        bS[e] = (gidx < NN * TT) ? bank[gidx] : 0.f;
    }
    __syncthreads();
    if (threadIdx.x < 128) {
        int n = n0 + threadIdx.x;
        if (n < NN) {
            float s = 0.f;
#pragma unroll
            for (int t = 0; t < TT; t++) { float v = bS[threadIdx.x * TT + t]; s += v * v; }
            g_banknorm[n] = s;
        }
    }
}

// ---------------- f32x2 helpers ----------------
__device__ __forceinline__ void fma2(unsigned long long &c, unsigned long long a, unsigned long long b) {
    asm("fma.rn.f32x2 %0, %1, %2, %0;" : "+l"(c) : "l"(a), "l"(b));
}
__device__ __forceinline__ unsigned long long pack2(float x, float y) {
    unsigned long long r; asm("mov.b64 %0, {%1,%2};" : "=l"(r) : "f"(x), "f"(y));
    return r;
}
__device__ __forceinline__ float2 unpack2(unsigned long long v) {
    float2 r; asm("mov.b64 {%0,%1}, %2;" : "=f"(r.x), "=f"(r.y) : "l"(v));
    return r;
}

// ---------------- f32x2 NT GEMM: 128x64 tile, 4x4(x2m) microtile, 3 blocks/SM ----------------
__global__ void __launch_bounds__(256, 3)
k_gemm_f32x2(const float* __restrict__ Aext, const float* __restrict__ Bm,
             int M, int Nmat, int Kdim, int lda, int ldb, int aSel) {
    const float* A = Aext;
    if (aSel == 1) A = g_e1; else if (aSel == 2) A = g_e2;

    const int BM = 128, BN = 64, BK = 16;
    __shared__ float As[BK][BM + 4];
    __shared__ float Bs[BK][BN + 4];

    int bm = blockIdx.x * BM, bn = blockIdx.y * BN;
    int s = blockIdx.z, Sn = gridDim.z;
    int kchunk = (((Kdim + Sn - 1) / Sn) + BK - 1) & ~(BK - 1);
    int k0 = s * kchunk, k1 = min(Kdim, k0 + kchunk);

    int tid = threadIdx.x;
    int tx = tid & 15, ty = tid >> 4;
    int alm = tid >> 1, alq = (tid & 1) * 8;
    int bln = tid >> 2, blq = (tid & 3) * 4;

    unsigned long long acc[4][4];
#pragma unroll
    for (int i = 0; i < 4; i++)
#pragma unroll
        for (int j = 0; j < 4; j++) acc[i][j] = 0ULL;

    if (k0 < k1) {
        float4 ar0, ar1, br0;
        {
            int kt = k0;
            int gk = kt + alq;
            const float* ap = A + (size_t)(bm + alm) * lda + gk;
            if (gk + 7 < k1) { ar0 = *(const float4*)ap; ar1 = *(const float4*)(ap + 4); }
            else {
                float t[8];
#pragma unroll
                for (int i = 0; i < 8; i++) t[i] = (gk + i < k1) ? ap[i] : 0.f;
                ar0 = make_float4(t[0], t[1], t[2], t[3]);
                ar1 = make_float4(t[4], t[5], t[6], t[7]);
            }
            int gkb = kt + blq;
            int brow = bn + bln;
            if (brow < Nmat && gkb + 3 < k1) br0 = *(const float4*)(Bm + (size_t)brow * ldb + gkb);
            else {
                float t[4];
#pragma unroll
                for (int i = 0; i < 4; i++)
                    t[i] = (brow < Nmat && gkb + i < k1) ? Bm[(size_t)brow * ldb + gkb + i] : 0.f;
                br0 = make_float4(t[0], t[1], t[2], t[3]);
            }
        }

        for (int kt = k0; kt < k1; kt += BK) {
            As[alq + 0][alm] = ar0.x; As[alq + 1][alm] = ar0.y;
            As[alq + 2][alm] = ar0.z; As[alq + 3][alm] = ar0.w;
            As[alq + 4][alm] = ar1.x; As[alq + 5][alm] = ar1.y;
            As[alq + 6][alm] = ar1.z; As[alq + 7][alm] = ar1.w;
            Bs[blq + 0][bln] = br0.x; Bs[blq + 1][bln] = br0.y;
            Bs[blq + 2][bln] = br0.z; Bs[blq + 3][bln] = br0.w;
            __syncthreads();

            int ktn = kt + BK;
            if (ktn < k1) {
                int gk = ktn + alq;
                const float* ap = A + (size_t)(bm + alm) * lda + gk;
                if (gk + 7 < k1) { ar0 = *(const float4*)ap; ar1 = *(const float4*)(ap + 4); }
                else {
                    float t[8];
#pragma unroll
                    for (int i = 0; i < 8; i++) t[i] = (gk + i < k1) ? ap[i] : 0.f;
                    ar0 = make_float4(t[0], t[1], t[2], t[3]);
                    ar1 = make_float4(t[4], t[5], t[6], t[7]);
                }
                int gkb = ktn + blq;
                int brow = bn + bln;
                if (brow < Nmat && gkb + 3 < k1) br0 = *(const float4*)(Bm + (size_t)brow * ldb + gkb);
                else {
                    float t[4];
#pragma unroll
                    for (int i = 0; i < 4; i++)
                        t[i] = (brow < Nmat && gkb + i < k1) ? Bm[(size_t)brow * ldb + gkb + i] : 0.f;
                    br0 = make_float4(t[0], t[1], t[2], t[3]);
                }
            }

#pragma unroll
            for (int kk = 0; kk < BK; kk++) {
                unsigned long long aP[4];
#pragma unroll
                for (int ip = 0; ip < 4; ip++)
                    aP[ip] = *(const unsigned long long*)&As[kk][ty * 8 + ip * 2];
                float4 bv = *(const float4*)&Bs[kk][tx * 4];
                unsigned long long b0 = pack2(bv.x, bv.x);
                unsigned long long b1 = pack2(bv.y, bv.y);
                unsigned long long b2 = pack2(bv.z, bv.z);
                unsigned long long b3 = pack2(bv.w, bv.w);
#pragma unroll
                for (int ip = 0; ip < 4; ip++) {
                    fma2(acc[ip][0], aP[ip], b0);
                    fma2(acc[ip][1], aP[ip], b1);
                    fma2(acc[ip][2], aP[ip], b2);
                    fma2(acc[ip][3], aP[ip], b3);
                }
            }
            __syncthreads();
        }
    }

    float* o = g_part + (size_t)s * BB * 256;
    int n0 = bn + tx * 4;
#pragma unroll
    for (int ip = 0; ip < 4; ip++) {
        int m0 = bm + ty * 8 + ip * 2;
        float2 c0 = unpack2(acc[ip][0]);
        float2 c1 = unpack2(acc[ip][1]);
        float2 c2 = unpack2(acc[ip][2]);
        float2 c3 = unpack2(acc[ip][3]);
        *(float4*)&o[(size_t)m0 * 256 + n0]       = make_float4(c0.x, c1.x, c2.x, c3.x);
        *(float4*)&o[(size_t)(m0 + 1) * 256 + n0] = make_float4(c0.y, c1.y, c2.y, c3.y);
    }
}

// reduce split-K partials + bias + optional softplus
__global__ void k_reduce_bias_act(int S, int Nreal, const float* __restrict__ bias,
                                  int act, int dstSel, int M) {
    int i = blockIdx.x * blockDim.x + threadIdx.x;
    int total = M * Nreal;
    if (i >= total) return;
    int m = i / Nreal, n = i - m * Nreal;
    float v = 0.f;
    for (int s = 0; s < S; s++) v += g_part[(size_t)s * BB * 256 + (size_t)m * 256 + n];
    v += bias[n];
    if (act == 1) v = (v > 0.f) ? v + log1pf(expf(-v)) : log1pf(expf(v));
    if (dstSel == 0)      g_e1  [(size_t)m * HH + n] = v;
    else if (dstSel == 1) g_e2  [(size_t)m * HH + n] = v;
    else                  g_lin3[(size_t)m * TT + n] = v;
}

// ---------------- theta BN stats ----------------
__global__ void k_bn_stats_theta() {
    int t = blockIdx.x;
    __shared__ float ssum[256], ssq[256];
    float s = 0.f, q = 0.f;
    for (int m = threadIdx.x; m < BB; m += 256) {
        float v = g_lin3[m * TT + t];
        s += v; q += v * v;
    }
    ssum[threadIdx.x] = s; ssq[threadIdx.x] = q;
    __syncthreads();
    for (int o = 128; o > 0; o >>= 1) {
        if (threadIdx.x < o) { ssum[threadIdx.x] += ssum[threadIdx.x + o]; ssq[threadIdx.x] += ssq[threadIdx.x + o]; }
        __syncthreads();
    }
    if (threadIdx.x == 0) {
        float mean = ssum[0] / BB;
        float var  = ssq[0] / BB - mean * mean;
        g_mean3[t] = mean;
        g_rstd3[t] = rsqrtf(var + EPSV);
    }
}

// ---------------- BN + softmax + VQ: one warp per batch row ----------------
__global__ void k_vq(const float* __restrict__ gm, const float* __restrict__ bm,
                     const float* __restrict__ E) {
    __shared__ float Es[TT * TT];
    __shared__ float sS[8][TT];
    int tid = threadIdx.x, lane = tid & 31, wid = tid >> 5;
    for (int i = tid; i < TT * TT; i += 256) Es[i] = E[i];
    __syncthreads();
    int b = blockIdx.x * 8 + wid;

    int t0 = lane, t1 = lane + 32;
    bool v0 = (t0 < TT), v1 = (t1 < TT);
    float th0 = v0 ? (g_lin3[b * TT + t0] - g_mean3[t0]) * g_rstd3[t0] * gm[t0] + bm[t0] : -CUDART_INF_F;
    float th1 = v1 ? (g_lin3[b * TT + t1] - g_mean3[t1]) * g_rstd3[t1] * gm[t1] + bm[t1] : -CUDART_INF_F;

    float mx = fmaxf(th0, th1);
#pragma unroll
    for (int o = 16; o > 0; o >>= 1) mx = fmaxf(mx, __shfl_xor_sync(0xffffffffu, mx, o));

    float ex0 = v0 ? expf(th0 - mx) : 0.f;
    float ex1 = v1 ? expf(th1 - mx) : 0.f;
    float sum = ex0 + ex1;
#pragma unroll
    for (int o = 16; o > 0; o >>= 1) sum += __shfl_xor_sync(0xffffffffu, sum, o);

    float s0 = ex0 / sum, s1 = ex1 / sum;
    if (v0) { g_soft[b * TT + t0] = s0; sS[wid][t0] = s0; }
    if (v1) { g_soft[b * TT + t1] = s1; sS[wid][t1] = s1; }

    float sn = s0 * s0 + (v1 ? s1 * s1 : 0.f);
#pragma unroll
    for (int o = 16; o > 0; o >>= 1) sn += __shfl_xor_sync(0xffffffffu, sn, o);
    if (lane == 0) g_snorm[b] = sn;
    __syncwarp();

    float d0 = CUDART_INF_F, d1 = CUDART_INF_F;
    if (v0) {
        float dot = 0.f, en = 0.f;
#pragma unroll
        for (int u = 0; u < TT; u++) { float e = Es[t0 * TT + u]; dot += e * sS[wid][u]; en += e * e; }
        d0 = en - 2.f * dot;
    }
    if (v1) {
        float dot = 0.f, en = 0.f;
#pragma unroll
        for (int u = 0; u < TT; u++) { float e = Es[t1 * TT + u]; dot += e * sS[wid][u]; en += e * e; }
        d1 = en - 2.f * dot;
    }
    float bd = d0; int bj = t0;
    if (d1 < bd) { bd = d1; bj = t1; }
#pragma unroll
    for (int o = 16; o > 0; o >>= 1) {
        float ov = __shfl_xor_sync(0xffffffffu, bd, o);
        int   oi = __shfl_xor_sync(0xffffffffu, bj, o);
        if (ov < bd || (ov == bd && oi < bj)) { bd = ov; bj = oi; }
    }
    int jmin = bj;
    if (lane == 0) { g_enc[b] = jmin; atomicAdd(&g_counts[jmin], 1); }

    float df0 = v0 ? (Es[jmin * TT + t0] - s0) : 0.f;
    float df1 = v1 ? (Es[jmin * TT + t1] - s1) : 0.f;
    float el = df0 * df0 + df1 * df1;
#pragma unroll
    for (int o = 16; o > 0; o >>= 1) el += __shfl_xor_sync(0xffffffffu, el, o);
    if (lane == 0) atomicAdd(&g_acc[1], (double)el);
}

// ---------------- decoder BN ----------------
__global__ void k_decbn(const float* __restrict__ gd, const float* __restrict__ bd) {
    __shared__ float cnt[TT];
    for (int i = threadIdx.x; i < TT; i += 256) cnt[i] = (float)g_counts[i];
    __syncthreads();
    int v = blockIdx.x * 256 + threadIdx.x;
    if (v >= VV) return;
    float m = 0.f, q = 0.f;
    for (int c = 0; c < TT; c++) {
        float z = g_zc[(size_t)c * VV + v];
        m += cnt[c] * z; q += cnt[c] * z * z;
    }
    m /= BB; q /= BB;
    float rstd = rsqrtf(q - m * m + EPSV);
    float gg = gd[v], bbv = bd[v];
    for (int c = 0; c < TT; c++) {
        g_zhat[(size_t)c * VV + v] = (g_zc[(size_t)c * VV + v] - m) * rstd * gg + bbv;
    }
}

__global__ void k_lse() {
    int c = blockIdx.x;
    __shared__ float sm[256];
    const float* z = g_zhat + (size_t)c * VV;
    float mx = -CUDART_INF_F;
    for (int v = threadIdx.x; v < VV; v += 256) mx = fmaxf(mx, z[v]);
    sm[threadIdx.x] = mx; __syncthreads();
    for (int o = 128; o > 0; o >>= 1) { if (threadIdx.x < o) sm[threadIdx.x] = fmaxf(sm[threadIdx.x], sm[threadIdx.x + o]); __syncthreads(); }
    mx = sm[0]; __syncthreads();
    float s = 0.f;
    for (int v = threadIdx.x; v < VV; v += 256) s += expf(z[v] - mx);
    sm[threadIdx.x] = s; __syncthreads();
    for (int o = 128; o > 0; o >>= 1) { if (threadIdx.x < o) sm[threadIdx.x] += sm[threadIdx.x + o]; __syncthreads(); }
    if (threadIdx.x == 0) g_lse[c] = mx + logf(sm[0]);
}

// ---------------- distance GEMM + fuse epilogue (f32x2, 128x64 tiles) ----------------
__global__ void k_fuse(const float* __restrict__ bank, const float* __restrict__ Mcos,
                       const float* __restrict__ Mcoo, const int* __restrict__ idx) {
    __shared__ float As[TT][128 + 4];
    __shared__ float Bs[TT][64 + 4];
    int bm = blockIdx.x * 128, bn = blockIdx.y * 64;
    int tid = threadIdx.x;

    for (int e = tid; e < 128 * TT; e += 256) {
        int r = e / TT, kk = e - r * TT;
        As[kk][r] = g_soft[(size_t)(bm + r) * TT + kk];
    }
    for (int e = tid; e < 64 * TT; e += 256) {
        int r = e / TT, kk = e - r * TT;
        int nn = bn + r;
        Bs[kk][r] = (nn < NN) ? bank[(size_t)nn * TT + kk] : 0.f;
    }
    __syncthreads();

    int tx = tid & 15, ty = tid >> 4;
    unsigned long long acc[4][4];
#pragma unroll
    for (int i = 0; i < 4; i++)
#pragma unroll
        for (int j = 0; j < 4; j++) acc[i][j] = 0ULL;

#pragma unroll
    for (int kk = 0; kk < TT; kk++) {
        unsigned long long aP[4];
#pragma unroll
        for (int ip = 0; ip < 4; ip++)
            aP[ip] = *(const unsigned long long*)&As[kk][ty * 8 + ip * 2];
        float4 bv = *(const float4*)&Bs[kk][tx * 4];
        unsigned long long b0 = pack2(bv.x, bv.x);
        unsigned long long b1 = pack2(bv.y, bv.y);
        unsigned long long b2 = pack2(bv.z, bv.z);
        unsigned long long b3 = pack2(bv.w, bv.w);
#pragma unroll
        for (int ip = 0; ip < 4; ip++) {
            fma2(acc[ip][0], aP[ip], b0);
            fma2(acc[ip][1], aP[ip], b1);
            fma2(acc[ip][2], aP[ip], b2);
            fma2(acc[ip][3], aP[ip], b3);
        }
    }

    int n0 = bn + tx * 4;
    bool nok = (n0 + 3 < NN);
    float bn0 = 0, bn1 = 0, bn2 = 0, bn3 = 0;
    if (nok) { float4 t4 = *(const float4*)&g_banknorm[n0]; bn0 = t4.x; bn1 = t4.y; bn2 = t4.z; bn3 = t4.w; }
#pragma unroll
    for (int ip = 0; ip < 4; ip++) {
        float2 c0 = unpack2(acc[ip][0]);
        float2 c1 = unpack2(acc[ip][1]);
        float2 c2 = unpack2(acc[ip][2]);
        float2 c3 = unpack2(acc[ip][3]);
#pragma unroll
        for (int h = 0; h < 2; h++) {
            int m = bm + ty * 8 + ip * 2 + h;
            float dd0 = h ? c0.y : c0.x;
            float dd1 = h ? c1.y : c1.x;
            float dd2 = h ? c2.y : c2.x;
            float dd3 = h ? c3.y : c3.x;
            int ib = idx[m];
            float sn = g_snorm[m];
            size_t cbase = (size_t)ib * NN;
            if (nok) {
                float4 mc = *(const float4*)&Mcos[cbase + n0];
                float4 mo = *(const float4*)&Mcoo[cbase + n0];
                float cost, tdd, bow;
                float4 fo;
                cost = sn + bn0 - 2.f * dd0; tdd = cost * cost;
                bow = c_RHO * mc.x + (1.f - c_RHO) * mo.x;
                fo.x = (n0     == ib) ? CUDART_INF_F : c_ETA * tdd + (1.f - c_ETA) * bow;
                cost = sn + bn1 - 2.f * dd1; tdd = cost * cost;
                bow = c_RHO * mc.y + (1.f - c_RHO) * mo.y;
                fo.y = (n0 + 1 == ib) ? CUDART_INF_F : c_ETA * tdd + (1.f - c_ETA) * bow;
                cost = sn + bn2 - 2.f * dd2; tdd = cost * cost;
                bow = c_RHO * mc.z + (1.f - c_RHO) * mo.z;
                fo.z = (n0 + 2 == ib) ? CUDART_INF_F : c_ETA * tdd + (1.f - c_ETA) * bow;
                cost = sn + bn3 - 2.f * dd3; tdd = cost * cost;
                bow = c_RHO * mc.w + (1.f - c_RHO) * mo.w;
                fo.w = (n0 + 3 == ib) ? CUDART_INF_F : c_ETA * tdd + (1.f - c_ETA) * bow;
                *(float4*)&g_fuse[(size_t)m * NN + n0] = fo;
            } else {
                float dds[4] = {dd0, dd1, dd2, dd3};
#pragma unroll
                for (int j = 0; j < 4; j++) {
                    int n = n0 + j;
                    if (n < NN) {
                        float cost = sn + g_banknorm[n] - 2.f * dds[j];
                        float tdd = cost * cost;
                        float bow = c_RHO * Mcos[cbase + n] + (1.f - c_RHO) * Mcoo[cbase + n];
                        float f = (n == ib) ? CUDART_INF_F : c_ETA * tdd + (1.f - c_ETA) * bow;
                        g_fuse[(size_t)m * NN + n] = f;
                    }
                }
            }
        }
    }
}

// ---------------- top-K via exact radix-select ----------------
__global__ void k_topk(const int* __restrict__ is_aug) {
    int b = blockIdx.x;
    const float* row = g_fuse + (size_t)b * NN;
    int tid = threadIdx.x;
    __shared__ unsigned hist[2048];
    __shared__ unsigned scanbuf[256];
    __shared__ unsigned s_prefix, s_need;
    __shared__ int s_cnt;
    if (tid == 0) { s_prefix = 0; s_need = KK; s_cnt = 0; }
    __syncthreads();

    for (int r = 0; r < 3; r++) {
        for (int i = tid; i < 2048; i += 256) hist[i] = 0;
        __syncthreads();
        unsigned pfx = s_prefix;
        for (int n4 = tid * 4; n4 < NN; n4 += 1024) {
            float4 x = *(const float4*)(row + n4);
            unsigned k4[4] = {__float_as_uint(x.x), __float_as_uint(x.y),
                              __float_as_uint(x.z), __float_as_uint(x.w)};
#pragma unroll
            for (int j = 0; j < 4; j++) {
                unsigned key = k4[j];
                if (r == 0) {
                    atomicAdd(&hist[key >> 21], 1u);
                } else if (r == 1) {
                    if ((key >> 21) == pfx) atomicAdd(&hist[(key >> 10) & 2047u], 1u);
                } else {
                    if ((key >> 10) == pfx) atomicAdd(&hist[key & 1023u], 1u);
                }
            }
        }
        __syncthreads();
        unsigned local = 0;
#pragma unroll
        for (int i = 0; i < 8; i++) local += hist[tid * 8 + i];
        scanbuf[tid] = local;
        __syncthreads();
        for (int o = 1; o < 256; o <<= 1) {
            unsigned v = (tid >= o) ? scanbuf[tid - o] : 0u;
            __syncthreads();
            scanbuf[tid] += v;
            __syncthreads();
        }
        unsigned incl = scanbuf[tid];
        unsigned excl = incl - local;
        unsigned need = s_need;
        if (excl < need && need <= incl) {
            unsigned cum = excl;
#pragma unroll
            for (int i = 0; i < 8; i++) {
                unsigned h = hist[tid * 8 + i];
                if (cum < need && need <= cum + h) {
                    unsigned bsel = (unsigned)(tid * 8 + i);
                    unsigned opfx = s_prefix;
                    s_prefix = (r == 0) ? bsel
                             : (r == 1) ? ((opfx << 11) | bsel)
                                        : ((opfx << 10) | bsel);
                    s_need = need - cum;
                    break;
                }
                cum += h;
            }
        }
        __syncthreads();
    }

    unsigned T = s_prefix;
    unsigned need = s_need;
    int aug = is_aug[0];
    int e = g_enc[b];

    for (int n4 = tid * 4; n4 < NN; n4 += 1024) {
        float4 x = *(const float4*)(row + n4);
        unsigned k4[4] = {__float_as_uint(x.x), __float_as_uint(x.y),
                          __float_as_uint(x.z), __float_as_uint(x.w)};
#pragma unroll
        for (int j = 0; j < 4; j++) {
            unsigned key = k4[j];
            int n = n4 + j;
            if (key < T) {
                if (aug) { atomicAdd(&g_w[n * 64 + e], 1); g_used[n] = 1; }
            } else if (key == T) {
                int p = atomicAdd(&s_cnt, 1);
                if (p < 2048) hist[p] = (unsigned)n;
            }
        }
    }
    __syncthreads();
    int cnt = min(s_cnt, 2048);
    if (aug) {
        for (int i = tid; i < cnt; i += 256) {
            unsigned my = hist[i];
            int rank = 0;
            for (int j = 0; j < cnt; j++) rank += (hist[j] < my);
            if (rank < (int)need) { atomicAdd(&g_w[my * 64 + e], 1); g_used[my] = 1; }
        }
    }
}

// ---------------- rec loss: merged rows + inputs kernel ----------------
__global__ void k_rec(const float* __restrict__ training, const float* __restrict__ inputs,
                      const int* __restrict__ is_aug) {
    int blk = blockIdx.x;
    int tid = threadIdx.x, lane = tid & 31, wid = tid >> 5;

    if (blk >= NN) {
        int b = blk - NN;
        int e = g_enc[b];
        const float* z  = g_zhat + (size_t)e * VV;
        const float* xr = inputs + (size_t)b * VV;
        float dotI = 0.f, sumI = 0.f;
        for (int v = tid * 4; v < VV; v += 256 * 4) {
            float4 x = *(const float4*)(xr + v);
            float4 zz = *(const float4*)(z + v);
            dotI += x.x * zz.x + x.y * zz.y + x.z * zz.z + x.w * zz.w;
            sumI += x.x + x.y + x.z + x.w;
        }
        __shared__ float r1[256], r2[256];
        r1[tid] = dotI; r2[tid] = sumI;
        __syncthreads();
        for (int o = 128; o > 0; o >>= 1) {
            if (tid < o) { r1[tid] += r1[tid + o]; r2[tid] += r2[tid + o]; }
            __syncthreads();
        }
        if (tid == 0) {
            double contrib = (double)g_lse[e] * (double)r2[0] - (double)r1[0];
            atomicAdd(&g_acc[0], contrib);
        }
        return;
    }

    if (is_aug[0] == 0) return;
    int n = blk;
    if (!g_used[n]) return;
    __shared__ float trS[VV];
    __shared__ int codes[64];
    __shared__ int wts[64];
    __shared__ int s_nc;
    __shared__ float red[256];
    __shared__ float s_S;
    __shared__ double warpc[8];
    if (tid == 0) s_nc = 0;
    if (tid < 8) warpc[tid] = 0.0;
    __syncthreads();
    if (tid < 64) {
        int w = g_w[n * 64 + tid];
        if (w > 0) { int pp = atomicAdd(&s_nc, 1); codes[pp] = tid; wts[pp] = w; }
    }
    const float* tr = training + (size_t)n * VV;
    float sloc = 0.f;
    for (int v = tid * 4; v < VV; v += 256 * 4) {
        float4 x = *(const float4*)(tr + v);
        *(float4*)&trS[v] = x;
        sloc += x.x + x.y + x.z + x.w;
    }
    red[tid] = sloc; __syncthreads();
    for (int o = 128; o > 0; o >>= 1) { if (tid < o) red[tid] += red[tid + o]; __syncthreads(); }
    if (tid == 0) s_S = red[0];
    __syncthreads();

    int nc = s_nc;
    float S = s_S;
    for (int ci = wid; ci < nc; ci += 8) {
        int c = codes[ci];
        const float* z = g_zhat + (size_t)c * VV;
        float d = 0.f;
        for (int v = lane * 4; v < VV; v += 128) {
            float4 x = *(const float4*)&trS[v];
            float4 zz = *(const float4*)(z + v);
            d += x.x * zz.x + x.y * zz.y + x.z * zz.z + x.w * zz.w;
        }
#pragma unroll
        for (int o = 16; o > 0; o >>= 1) d += __shfl_xor_sync(0xffffffffu, d, o);
        if (lane == 0) warpc[wid] += (double)wts[ci] * ((double)g_lse[c] * (double)S - (double)d);
    }
    __syncthreads();
    if (tid == 0) {
        double contrib = 0.0;
#pragma unroll
        for (int w = 0; w < 8; w++) contrib += warpc[w];
        if (nc > 0) atomicAdd(&g_acc[0], contrib * (double)(ALPHAV / (float)KK));
    }
}

// ---------------- final ----------------
__global__ void k_final(float* out) {
    if (threadIdx.x == 0) {
        double rec = g_acc[0] / (double)BB;
        double ql  = (1.0 + (double)CCV) * (g_acc[1] / (double)(BB * TT));
        out[0] = (float)(rec + ql);
    }
}

// ---------------- launch ----------------
extern "C" void kernel_launch(void* const* d_in, const int* in_sizes, int n_in,
                              void* d_out, int out_size) {
    const int*   idx      = (const int*)  d_in[0];
    const float* inputs   = (const float*)d_in[1];
    const int*   is_aug   = (const int*)  d_in[2];
    const float* training = (const float*)d_in[3];
    const float* Mcos     = (const float*)d_in[4];
    const float* Mcoo     = (const float*)d_in[5];
    const float* bank     = (const float*)d_in[6];
    const float* W11      = (const float*)d_in[7];
    const float* b11      = (const float*)d_in[8];
    const float* W12      = (const float*)d_in[9];
    const float* b12      = (const float*)d_in[10];
    const float* W21      = (const float*)d_in[11];
    const float* b21      = (const float*)d_in[12];
    const float* gm       = (const float*)d_in[13];
    const float* bm       = (const float*)d_in[14];
    const float* gd       = (const float*)d_in[15];
    const float* bd       = (const float*)d_in[16];
    const float* Wd       = (const float*)d_in[17];
    const float* E        = (const float*)d_in[18];
    float* out = (float*)d_out;

    k_setup<<<(NN * 64 + 255) / 256, 256>>>();
    k_zc<<<(VV + 127) / 128, 128>>>(Wd, E);
    k_banknorm<<<(NN + 127) / 128, 256>>>(bank);

    // launch 4 (ncu-captured): encoder layer 1, 4x4 microtile, 3 blocks/SM, split-K=24 -> 768 blocks
    k_gemm_f32x2<<<dim3(8, 4, 24), 256>>>(inputs, W11, BB, HH, VV, VV, VV, 0);
    k_reduce_bias_act<<<(BB * HH + 255) / 256, 256>>>(24, HH, b11, 1, 0, BB);

    // encoder layer 2
    k_gemm_f32x2<<<dim3(8, 4, 8), 256>>>(nullptr, W12, BB, HH, HH, HH, HH, 1);
    k_reduce_bias_act<<<(BB * HH + 255) / 256, 256>>>(8, HH, b12, 1, 1, BB);

    // theta linear
    k_gemm_f32x2<<<dim3(8, 1, 8), 256>>>(nullptr, W21, BB, TT, HH, HH, HH, 2);
    k_reduce_bias_act<<<(BB * TT + 255) / 256, 256>>>(8, TT, b21, 0, 2, BB);

    // BN stats + VQ
    k_bn_stats_theta<<<TT, 256>>>();
    k_vq<<<BB / 8, 256>>>(gm, bm, E);

    // decoder per-code pipeline
    k_decbn<<<(VV + 255) / 256, 256>>>(gd, bd);
    k_lse<<<TT, 256>>>();

    // augmentation: fuse + radix-select topk
    k_fuse<<<dim3(8, (NN + 63) / 64), 256>>>(bank, Mcos, Mcoo, idx);
    k_topk<<<BB, 256>>>(is_aug);

    // rec loss (merged rows + inputs)
    k_rec<<<NN + BB, 256>>>(training, inputs, is_aug);
    k_final<<<1, 1>>>(out);
}